// round 12
// baseline (speedup 1.0000x reference)
#include <cuda_runtime.h>
#include <cuda_fp16.h>
#include <cstdint>
#include <mma.h>

using namespace nvcuda;

#define ATTN_SCALE 0.044194173824159216f  // 1/sqrt(512)
#define TH_LD 520
#define SS_LD 100

// ---------------- static device scratch ----------------
__device__ __align__(16) __half g_xhi  [768 * 512],   g_xlo  [768 * 512];
__device__ __align__(16) __half g_siwhi[1536 * 512],  g_siwlo[1536 * 512];
__device__ __align__(16) __half g_cWkhi[512 * 512],   g_cWklo[512 * 512];
__device__ __align__(16) __half g_cWvhi[512 * 512],   g_cWvlo[512 * 512];
__device__ __align__(16) __half g_cWqThi[512 * 512],  g_cWqTlo[512 * 512];
__device__ __align__(16) __half g_cowhi[512 * 512],   g_cowlo[512 * 512];
__device__ __align__(16) float  g_qkv  [768 * 1536];
__device__ __align__(16) __half g_W2hi [512 * 512],   g_W2lo [512 * 512];
__device__ __align__(16) float  g_bqk  [512];
__device__ __align__(16) __half g_qkh  [768 * 512];
__device__ __align__(16) __half g_Wovh [512 * 512];
__device__ __align__(16) float  g_bov  [512];
__device__ __align__(16) float  g_imgf [64 * 512];
__device__ __align__(16) __half g_rch  [(size_t)64 * 1000 * 512];
__device__ __align__(16) __half g_txth [(size_t)64 * 1000 * 512];
__device__ __align__(16) float  g_part [64 * 512];
__device__ __align__(16) float  g_h    [64 * 512];

// ---------------- helpers ----------------
__device__ __forceinline__ void cpasync16(uint32_t dst, const void* src) {
    asm volatile("cp.async.cg.shared.global [%0], [%1], 16;"
                 :: "r"(dst), "l"(__cvta_generic_to_global(src)));
}
__device__ __forceinline__ uint32_t smem_u32(const void* p) {
    uint32_t a;
    asm("{ .reg .u64 t; cvta.to.shared.u64 t, %1; cvt.u32.u64 %0, t; }" : "=r"(a) : "l"(p));
    return a;
}
#define CP_COMMIT() asm volatile("cp.async.commit_group;" ::: "memory")
#define CP_WAIT0()  asm volatile("cp.async.wait_group 0;" ::: "memory")

__device__ __forceinline__ void split_f(float x, __half& h, __half& l) {
    h = __float2half(x);
    l = __float2half(x - __half2float(h));
}

// =======================================================================
// MEGA conversion kernel (launch #1):
//   [0,1952)     : split converts (x|siw|cWk|cWv|cow) + zero g_part
//   [1952,2208)  : cWq transpose-split
//   [2208,2224)  : bqk
// =======================================================================
__global__ void megaconv(const float* __restrict__ x, const float* __restrict__ siw,
                         const float* __restrict__ ciw, const float* __restrict__ cow,
                         const float* __restrict__ cib)
{
    __shared__ float sred[8][33];
    __shared__ float tt[32][33];
    const int blk = blockIdx.x, tid = threadIdx.x;

    if (blk < 1952) {
        const size_t N1 = 98304, N2 = N1 + 196608, N3 = N2 + 65536, N4 = N3 + 65536,
                     N5 = N4 + 65536, N6 = N5 + 8192;
        size_t u = (size_t)blk * 256 + tid;
        if (u >= N6) return;
        if (u >= N5) { ((float4*)g_part)[u - N5] = make_float4(0.f, 0.f, 0.f, 0.f); return; }
        const float* src; __half* hi; __half* lo; size_t o;
        if (u < N1)      { src = x;                hi = g_xhi;   lo = g_xlo;   o = u; }
        else if (u < N2) { src = siw;              hi = g_siwhi; lo = g_siwlo; o = u - N1; }
        else if (u < N3) { src = ciw + 512 * 512;  hi = g_cWkhi; lo = g_cWklo; o = u - N2; }
        else if (u < N4) { src = ciw + 1024 * 512; hi = g_cWvhi; lo = g_cWvlo; o = u - N3; }
        else             { src = cow;              hi = g_cowhi; lo = g_cowlo; o = u - N4; }
        float4 v = ((const float4*)src)[o];
        __half h0, l0, h1, l1, h2, l2, h3, l3;
        split_f(v.x, h0, l0); split_f(v.y, h1, l1);
        split_f(v.z, h2, l2); split_f(v.w, h3, l3);
        __half2* oh = (__half2*)(hi + o * 4);
        __half2* ol = (__half2*)(lo + o * 4);
        oh[0] = __halves2half2(h0, h1); oh[1] = __halves2half2(h2, h3);
        ol[0] = __halves2half2(l0, l1); ol[1] = __halves2half2(l2, l3);
    } else if (blk < 2208) {
        int b = blk - 1952;
        const int tx = tid & 31, ty = tid >> 5;
        const int bx = (b & 15) * 32, by = (b >> 4) * 32;
        #pragma unroll
        for (int j = 0; j < 4; j++)
            tt[ty + j * 8][tx] = ciw[(size_t)(by + ty + j * 8) * 512 + bx + tx];
        __syncthreads();
        #pragma unroll
        for (int j = 0; j < 4; j++) {
            float v = tt[tx][ty + j * 8];
            __half h, l; split_f(v, h, l);
            size_t o = (size_t)(bx + ty + j * 8) * 512 + by + tx;
            g_cWqThi[o] = h; g_cWqTlo[o] = l;
        }
    } else {
        int b = blk - 2208;
        const int dd = tid & 31, eg = tid >> 5;
        const int d = b * 32 + dd;
        const float* cWk = ciw + 512 * 512;
        float s = 0.f;
        const int e0 = eg * 64;
        #pragma unroll 8
        for (int e = e0; e < e0 + 64; e++) s += cib[e] * cWk[(size_t)e * 512 + d];
        sred[eg][dd] = s;
        __syncthreads();
        if (eg == 0) {
            float t = 0.f;
            #pragma unroll
            for (int i = 0; i < 8; i++) t += sred[i][dd];
            g_bqk[d] = t * ATTN_SCALE;
        }
    }
}

// =======================================================================
// Split-fp16 GEMM body (weights)
// =======================================================================
__device__ __forceinline__ void hg3_body(
    __half* Ash, __half* Asl, __half* Bsh, __half* Bsl, float* Cs,
    const __half* __restrict__ Ahi, const __half* __restrict__ Alo,
    const __half* __restrict__ Bhi, const __half* __restrict__ Blo, int bt,
    const float* __restrict__ bias, float scale,
    float* __restrict__ Cf, __half* __restrict__ Chi, __half* __restrict__ Clo,
    int N, int K, int m0, int n0)
{
    const int tid = threadIdx.x, warp = tid >> 5;
    const int wr = warp >> 1, wc = warp & 1;

    wmma::fragment<wmma::accumulator, 16, 16, 16, float> acc[2];
    wmma::fill_fragment(acc[0], 0.f);
    wmma::fill_fragment(acc[1], 0.f);

    uint4 rah[2], ral[2], rbh[2], rbl[2];
    #pragma unroll
    for (int i = 0; i < 2; i++) {
        int f = tid + i * 256, r = f >> 3, v = f & 7;
        rah[i] = ((const uint4*)(Ahi + (size_t)(m0 + r) * K))[v];
        ral[i] = ((const uint4*)(Alo + (size_t)(m0 + r) * K))[v];
        if (bt) {
            rbh[i] = ((const uint4*)(Bhi + (size_t)(n0 + r) * K))[v];
            rbl[i] = ((const uint4*)(Blo + (size_t)(n0 + r) * K))[v];
        } else {
            rbh[i] = ((const uint4*)(Bhi + (size_t)r * N + n0))[v];
            rbl[i] = ((const uint4*)(Blo + (size_t)r * N + n0))[v];
        }
    }
    const int nk = K >> 6;
    for (int kc = 0; kc < nk; kc++) {
        #pragma unroll
        for (int i = 0; i < 2; i++) {
            int f = tid + i * 256, r = f >> 3, v = f & 7;
            *((uint4*)(Ash + r * 72) + v) = rah[i];
            *((uint4*)(Asl + r * 72) + v) = ral[i];
            *((uint4*)(Bsh + r * 72) + v) = rbh[i];
            *((uint4*)(Bsl + r * 72) + v) = rbl[i];
        }
        __syncthreads();
        if (kc + 1 < nk) {
            int kk = (kc + 1) << 6;
            #pragma unroll
            for (int i = 0; i < 2; i++) {
                int f = tid + i * 256, r = f >> 3, v = f & 7;
                rah[i] = ((const uint4*)(Ahi + (size_t)(m0 + r) * K + kk))[v];
                ral[i] = ((const uint4*)(Alo + (size_t)(m0 + r) * K + kk))[v];
                if (bt) {
                    rbh[i] = ((const uint4*)(Bhi + (size_t)(n0 + r) * K + kk))[v];
                    rbl[i] = ((const uint4*)(Blo + (size_t)(n0 + r) * K + kk))[v];
                } else {
                    rbh[i] = ((const uint4*)(Bhi + (size_t)(kk + r) * N + n0))[v];
                    rbl[i] = ((const uint4*)(Blo + (size_t)(kk + r) * N + n0))[v];
                }
            }
        }
        #pragma unroll
        for (int ks = 0; ks < 4; ks++) {
            wmma::fragment<wmma::matrix_a, 16, 16, 16, __half, wmma::row_major> afh, afl;
            wmma::load_matrix_sync(afh, Ash + (wr * 16) * 72 + ks * 16, 72);
            wmma::load_matrix_sync(afl, Asl + (wr * 16) * 72 + ks * 16, 72);
            #pragma unroll
            for (int j = 0; j < 2; j++) {
                if (bt) {
                    wmma::fragment<wmma::matrix_b, 16, 16, 16, __half, wmma::col_major> bfh, bfl;
                    wmma::load_matrix_sync(bfh, Bsh + ((wc * 2 + j) * 16) * 72 + ks * 16, 72);
                    wmma::load_matrix_sync(bfl, Bsl + ((wc * 2 + j) * 16) * 72 + ks * 16, 72);
                    wmma::mma_sync(acc[j], afh, bfh, acc[j]);
                    wmma::mma_sync(acc[j], afh, bfl, acc[j]);
                    wmma::mma_sync(acc[j], afl, bfh, acc[j]);
                } else {
                    wmma::fragment<wmma::matrix_b, 16, 16, 16, __half, wmma::row_major> bfh, bfl;
                    wmma::load_matrix_sync(bfh, Bsh + (ks * 16) * 72 + (wc * 2 + j) * 16, 72);
                    wmma::load_matrix_sync(bfl, Bsl + (ks * 16) * 72 + (wc * 2 + j) * 16, 72);
                    wmma::mma_sync(acc[j], afh, bfh, acc[j]);
                    wmma::mma_sync(acc[j], afh, bfl, acc[j]);
                    wmma::mma_sync(acc[j], afl, bfh, acc[j]);
                }
            }
        }
        __syncthreads();
    }
    wmma::store_matrix_sync(Cs + (wr * 16) * 68 + wc * 32,      acc[0], 68, wmma::mem_row_major);
    wmma::store_matrix_sync(Cs + (wr * 16) * 68 + wc * 32 + 16, acc[1], 68, wmma::mem_row_major);
    __syncthreads();
    for (int i = tid; i < 4096; i += 256) {
        int r = i >> 6, n = i & 63;
        float v = Cs[r * 68 + n] * scale + (bias ? bias[n0 + n] : 0.f);
        size_t m = m0 + r;
        if (Cf)  Cf[m * N + n0 + n] = v;
        if (Chi) {
            __half h = __float2half(v);
            Chi[m * N + n0 + n] = h;
            if (Clo) Clo[m * N + n0 + n] = __float2half(v - __half2float(h));
        }
    }
}

// launch #2: qkv [0,288) | W2 [288,352) | Wov [352,416)
__global__ void hgemm3_w(const float* __restrict__ sib)
{
    __shared__ __half Ash[64 * 72], Asl[64 * 72], Bsh[64 * 72], Bsl[64 * 72];
    __shared__ float  Cs[64 * 68];
    int id = blockIdx.x;
    if (id < 288) {
        hg3_body(Ash, Asl, Bsh, Bsl, Cs, g_xhi, g_xlo, g_siwhi, g_siwlo, 1, sib, 1.f,
                 g_qkv, nullptr, nullptr, 1536, 512, (id / 24) * 64, (id % 24) * 64);
    } else if (id < 352) {
        id -= 288;
        hg3_body(Ash, Asl, Bsh, Bsl, Cs, g_cWqThi, g_cWqTlo, g_cWkhi, g_cWklo, 0, nullptr,
                 ATTN_SCALE, nullptr, g_W2hi, g_W2lo, 512, 512, (id / 8) * 64, (id % 8) * 64);
    } else {
        id -= 352;
        hg3_body(Ash, Asl, Bsh, Bsl, Cs, g_cowhi, g_cowlo, g_cWvhi, g_cWvlo, 0, nullptr,
                 1.f, nullptr, g_Wovh, nullptr, 512, 512, (id / 8) * 64, (id % 8) * 64);
    }
}

// =======================================================================
// launch #3: self-attention + xs + qk + image feature, all per batch b.
// 256 threads. smem: q/o 12x512 | k/xs 12x512 | v 12x512 | S 144.
// =======================================================================
__global__ void self_attn_mega(const float* __restrict__ sow, const float* __restrict__ sob)
{
    extern __shared__ float sh[];
    float* q  = sh;                 // later reused for o
    float* k  = sh + 12 * 512;      // later reused for xs
    float* v  = sh + 2 * 12 * 512;
    float* S  = sh + 3 * 12 * 512;
    const int b = blockIdx.x, tid = threadIdx.x;
    const int warp = tid >> 5, lane = tid & 31;

    for (int i = tid; i < 12 * 512; i += 256) {
        int l = i >> 9, d = i & 511;
        const float* row = g_qkv + (size_t)(l * 64 + b) * 1536;
        q[i] = row[d]; k[i] = row[512 + d]; v[i] = row[1024 + d];
    }
    __syncthreads();
    for (int i = tid; i < 144; i += 256) {
        int l = i / 12, m = i - l * 12;
        const float* qp = q + l * 512;
        const float* kp = k + m * 512;
        float s = 0.f;
        for (int e = 0; e < 512; e++) s += qp[e] * kp[e];
        S[i] = s * ATTN_SCALE;
    }
    __syncthreads();
    if (tid < 12) {
        float mx = -1e30f;
        for (int m = 0; m < 12; m++) mx = fmaxf(mx, S[tid * 12 + m]);
        float e[12], sum = 0.f;
        for (int m = 0; m < 12; m++) { e[m] = expf(S[tid * 12 + m] - mx); sum += e[m]; }
        float inv = 1.f / sum;
        for (int m = 0; m < 12; m++) S[tid * 12 + m] = e[m] * inv;
    }
    __syncthreads();
    // o = attn @ v  -> overwrite q (q fully consumed by S)
    float obuf[24];
    for (int i = tid, t = 0; i < 12 * 512; i += 256, t++) {
        int l = i >> 9, d = i & 511;
        float o = 0.f;
        #pragma unroll
        for (int m = 0; m < 12; m++) o += S[l * 12 + m] * v[m * 512 + d];
        obuf[t] = o;
    }
    __syncthreads();
    for (int i = tid, t = 0; i < 12 * 512; i += 256, t++) q[i] = obuf[t];
    __syncthreads();
    float* o  = q;
    float* xs = k;

    // xs[l,d] = sum_e o[l,e]*sow[d,e] + sob[d]   (warp per row d, shfl reduce)
    for (int d = warp; d < 512; d += 8) {
        const float* srow = sow + (size_t)d * 512;
        float part[12];
        #pragma unroll
        for (int l = 0; l < 12; l++) part[l] = 0.f;
        for (int e = lane; e < 512; e += 32) {
            float sv = srow[e];
            #pragma unroll
            for (int l = 0; l < 12; l++) part[l] += o[l * 512 + e] * sv;
        }
        #pragma unroll
        for (int l = 0; l < 12; l++)
            #pragma unroll
            for (int off = 16; off > 0; off >>= 1)
                part[l] += __shfl_xor_sync(0xffffffff, part[l], off);
        if (lane == 0) {
            float bias = sob[d];
            #pragma unroll
            for (int l = 0; l < 12; l++) xs[l * 512 + d] = part[l] + bias;
        }
    }
    __syncthreads();

    // image feature (exact fp32): row l=11
    for (int i = tid; i < 512; i += 256) g_imgf[b * 512 + i] = xs[11 * 512 + i];

    // qk[l,n] = sum_d xs[l,d]*W2[d,n] + bqk[n]  (output stationary, warp owns 64 n)
    {
        const int n0 = warp * 64;
        const int n1 = n0 + lane, n2 = n0 + 32 + lane;
        float a1[12], a2[12];
        #pragma unroll
        for (int l = 0; l < 12; l++) { a1[l] = 0.f; a2[l] = 0.f; }
        for (int d = 0; d < 512; d++) {
            float w1 = __half2float(g_W2hi[(size_t)d * 512 + n1]) +
                       __half2float(g_W2lo[(size_t)d * 512 + n1]);
            float w2 = __half2float(g_W2hi[(size_t)d * 512 + n2]) +
                       __half2float(g_W2lo[(size_t)d * 512 + n2]);
            #pragma unroll
            for (int l = 0; l < 12; l++) {
                float xv = xs[l * 512 + d];
                a1[l] += xv * w1;
                a2[l] += xv * w2;
            }
        }
        float b1 = g_bqk[n1], b2 = g_bqk[n2];
        #pragma unroll
        for (int l = 0; l < 12; l++) {
            g_qkh[(size_t)(b * 12 + l) * 512 + n1] = __float2half(a1[l] + b1);
            g_qkh[(size_t)(b * 12 + l) * 512 + n2] = __float2half(a2[l] + b2);
        }
    }
}

// launch #4: bov (needed only by txt_gemm)
__global__ void bov_kernel(const float* __restrict__ cow,
                           const float* __restrict__ cib,
                           const float* __restrict__ cob)
{
    int warp = threadIdx.x >> 5, lane = threadIdx.x & 31;
    int i = blockIdx.x * 8 + warp;
    const float* cbv = cib + 1024;
    float s = 0.f;
    for (int e = lane; e < 512; e += 32) s += cow[i * 512 + e] * cbv[e];
    #pragma unroll
    for (int o = 16; o > 0; o >>= 1) s += __shfl_xor_sync(0xffffffff, s, o);
    if (lane == 0) g_bov[i] = s + cob[i];
}

// =======================================================================
// launch #5: fused cross-attention (ncu target)
// =======================================================================
#define AQ0 99840
#define AQB 27648
#define WSMOFF 176640

__global__ void attn_cls_kernel(const float* __restrict__ textf)
{
    extern __shared__ char smc[];
    __half* th  = (__half*)smc;
    float*  Ss  = (float*)(smc + AQ0);
    __half* wsm = (__half*)(smc + WSMOFF);
    const uint32_t aqs = smem_u32(smc) + AQ0;
    const int tid  = threadIdx.x;
    const int warp = tid >> 5;
    const int c    = blockIdx.x;
    const int wr = warp >> 1, wc = warp & 1;

    {
        const float4* src = (const float4*)(textf + (size_t)c * (96 * 512));
        for (int i = tid; i < 96 * 128; i += 256) {
            int row = i >> 7, v = i & 127;
            float4 f = src[row * 128 + v];
            __half2* dst = (__half2*)(th + row * TH_LD + v * 4);
            dst[0] = __floats2half2_rn(f.x, f.y);
            dst[1] = __floats2half2_rn(f.z, f.w);
        }
    }
    __syncthreads();

    for (int mch = 0; mch < 4; mch++) {
        const int b0 = mch * 16;
        const __half* qbase = g_qkh + (size_t)(b0 * 12) * 512;

        #pragma unroll
        for (int i = 0; i < 6; i++) {
            int f = tid + i * 256, r = f >> 3, v = f & 7;
            cpasync16(aqs + r * 144 + v * 16, qbase + (size_t)r * 512 + v * 8);
        }
        CP_COMMIT();

        wmma::fragment<wmma::accumulator, 16, 16, 16, float> acc[3][3];
        #pragma unroll
        for (int i = 0; i < 3; i++)
            #pragma unroll
            for (int j = 0; j < 3; j++) wmma::fill_fragment(acc[i][j], 0.f);

        for (int kc = 0; kc < 8; kc++) {
            CP_WAIT0();
            __syncthreads();
            if (kc < 7) {
                uint32_t nbuf = aqs + ((kc + 1) & 1) * AQB;
                #pragma unroll
                for (int i = 0; i < 6; i++) {
                    int f = tid + i * 256, r = f >> 3, v = f & 7;
                    cpasync16(nbuf + r * 144 + v * 16,
                              qbase + (size_t)r * 512 + (kc + 1) * 64 + v * 8);
                }
                CP_COMMIT();
            }
            const __half* aq = (const __half*)(smc + AQ0 + (kc & 1) * AQB);
            #pragma unroll
            for (int ks = 0; ks < 4; ks++) {
                wmma::fragment<wmma::matrix_a, 16, 16, 16, __half, wmma::row_major> af[3];
                #pragma unroll
                for (int i = 0; i < 3; i++)
                    wmma::load_matrix_sync(af[i], aq + ((wr * 3 + i) * 16) * 72 + ks * 16, 72);
                #pragma unroll
                for (int j = 0; j < 3; j++) {
                    wmma::fragment<wmma::matrix_b, 16, 16, 16, __half, wmma::col_major> bf;
                    wmma::load_matrix_sync(bf, th + ((wc * 3 + j) * 16) * TH_LD + kc * 64 + ks * 16, TH_LD);
                    #pragma unroll
                    for (int i = 0; i < 3; i++) wmma::mma_sync(acc[i][j], af[i], bf, acc[i][j]);
                }
            }
        }
        __syncthreads();
        #pragma unroll
        for (int i = 0; i < 3; i++)
            #pragma unroll
            for (int j = 0; j < 3; j++)
                wmma::store_matrix_sync(Ss + ((wr * 3 + i) * 16) * SS_LD + (wc * 3 + j) * 16,
                                        acc[i][j], SS_LD, wmma::mem_row_major);
        __syncthreads();

        if (tid < 128) {
            int bl = tid >> 3, t = tid & 7;
            float wacc[12];
            #pragma unroll
            for (int m = 0; m < 12; m++) wacc[m] = 0.f;
            for (int l = 0; l < 12; l++) {
                int base = (bl * 12 + l) * SS_LD + t;
                float vals[12], mx = -1e30f;
                #pragma unroll
                for (int m = 0; m < 12; m++) { vals[m] = Ss[base + m * 8]; mx = fmaxf(mx, vals[m]); }
                float sum = 0.f;
                #pragma unroll
                for (int m = 0; m < 12; m++) { vals[m] = __expf(vals[m] - mx); sum += vals[m]; }
                float inv = 1.f / sum;
                #pragma unroll
                for (int m = 0; m < 12; m++) wacc[m] += vals[m] * inv;
            }
            #pragma unroll
            for (int m = 0; m < 12; m++)
                wsm[bl * 96 + m * 8 + t] = __float2half(wacc[m] * (1.f / 96.f));
        }
        __syncthreads();

        {
            wmma::fragment<wmma::accumulator, 16, 16, 16, float> rca[4];
            #pragma unroll
            for (int j = 0; j < 4; j++) wmma::fill_fragment(rca[j], 0.f);
            #pragma unroll
            for (int kt = 0; kt < 6; kt++) {
                wmma::fragment<wmma::matrix_a, 16, 16, 16, __half, wmma::row_major> af;
                wmma::load_matrix_sync(af, wsm + kt * 16, 96);
                #pragma unroll
                for (int j = 0; j < 4; j++) {
                    wmma::fragment<wmma::matrix_b, 16, 16, 16, __half, wmma::row_major> bf;
                    wmma::load_matrix_sync(bf, th + (kt * 16) * TH_LD + (warp * 4 + j) * 16, TH_LD);
                    wmma::mma_sync(rca[j], af, bf, rca[j]);
                }
            }
            #pragma unroll
            for (int j = 0; j < 4; j++)
                wmma::store_matrix_sync(Ss + (warp * 4 + j) * 16, rca[j], TH_LD, wmma::mem_row_major);
        }
        __syncthreads();

        for (int i = tid; i < 16 * 512; i += 256) {
            int bl = i >> 9, d = i & 511;
            g_rch[((size_t)(b0 + bl) * 1000 + c) * 512 + d] = __float2half(Ss[bl * TH_LD + d]);
        }
        __syncthreads();
    }
}

// =======================================================================
// txt = rc @ Wov^T + bov -> fp16, fused column-sq-sums. grid (4,500).
// =======================================================================
__global__ void txt_gemm_kernel()
{
    __shared__ __half As[128 * 72];
    __shared__ __half Bs[128 * 72];
    __shared__ float  stg[8][16 * 20];
    __shared__ float  sq[2][128];
    const int tid = threadIdx.x, warp = tid >> 5, lane = tid & 31;
    const size_t m0 = (size_t)blockIdx.y * 128;
    const int n0 = blockIdx.x * 128;
    const int wr = warp >> 1, wc = warp & 1;
    const int b0f = (int)(m0 / 1000);
    uint4 ra[4], rb[4];
    wmma::fragment<wmma::accumulator, 16, 16, 16, float> acc[2][4];
    #pragma unroll
    for (int i = 0; i < 2; i++)
        #pragma unroll
        for (int j = 0; j < 4; j++) wmma::fill_fragment(acc[i][j], 0.f);

    #pragma unroll
    for (int i = 0; i < 4; i++) {
        int f = tid + i * 256, r = f >> 3, v = f & 7;
        ra[i] = ((const uint4*)(g_rch + (m0 + r) * 512))[v];
        rb[i] = ((const uint4*)(g_Wovh + (size_t)(n0 + r) * 512))[v];
    }
    for (int kc = 0; kc < 8; kc++) {
        #pragma unroll
        for (int i = 0; i < 4; i++) {
            int f = tid + i * 256, r = f >> 3, v = f & 7;
            *((uint4*)(As + r * 72) + v) = ra[i];
            *((uint4*)(Bs + r * 72) + v) = rb[i];
        }
        __syncthreads();
        if (kc < 7) {
            int kk = (kc + 1) * 64;
            #pragma unroll
            for (int i = 0; i < 4; i++) {
                int f = tid + i * 256, r = f >> 3, v = f & 7;
                ra[i] = ((const uint4*)(g_rch + (m0 + r) * 512 + kk))[v];
                rb[i] = ((const uint4*)(g_Wovh + (size_t)(n0 + r) * 512 + kk))[v];
            }
        }
        #pragma unroll
        for (int ks = 0; ks < 4; ks++) {
            wmma::fragment<wmma::matrix_a, 16, 16, 16, __half, wmma::row_major> af[2];
            #pragma unroll
            for (int i = 0; i < 2; i++)
                wmma::load_matrix_sync(af[i], As + ((wr * 2 + i) * 16) * 72 + ks * 16, 72);
            #pragma unroll
            for (int j = 0; j < 4; j++) {
                wmma::fragment<wmma::matrix_b, 16, 16, 16, __half, wmma::col_major> bf;
                wmma::load_matrix_sync(bf, Bs + ((wc * 4 + j) * 16) * 72 + ks * 16, 72);
                #pragma unroll
                for (int i = 0; i < 2; i++) wmma::mma_sync(acc[i][j], af[i], bf, acc[i][j]);
            }
        }
        __syncthreads();
    }
    ((float*)sq)[tid] = 0.f;
    __syncthreads();
    float sq0[4] = {0.f, 0.f, 0.f, 0.f};
    float sq1[4] = {0.f, 0.f, 0.f, 0.f};
    #pragma unroll
    for (int i = 0; i < 2; i++)
        #pragma unroll
        for (int j = 0; j < 4; j++) {
            wmma::store_matrix_sync(stg[warp], acc[i][j], 20, wmma::mem_row_major);
            __syncwarp();
            #pragma unroll
            for (int e = 0; e < 8; e++) {
                int f = lane + e * 32, r = f >> 4, cc = f & 15;
                int n = n0 + (wc * 4 + j) * 16 + cc;
                size_t m = m0 + (wr * 2 + i) * 16 + r;
                float v = stg[warp][r * 20 + cc] + g_bov[n];
                g_txth[m * 512 + n] = __float2half(v);
                int bb = (int)(m / 1000) - b0f;
                if (bb == 0) sq0[j] += v * v; else sq1[j] += v * v;
            }
            __syncwarp();
        }
    #pragma unroll
    for (int j = 0; j < 4; j++) {
        int nl = (wc * 4 + j) * 16 + (lane & 15);
        atomicAdd(&sq[0][nl], sq0[j]);
        atomicAdd(&sq[1][nl], sq1[j]);
    }
    __syncthreads();
    if (tid < 128) {
        #pragma unroll
        for (int s = 0; s < 2; s++) {
            int b = b0f + s;
            if (b < 64) atomicAdd(&g_part[b * 512 + n0 + tid], sq[s][tid]);
        }
    }
}

__global__ void make_h_kernel()
{
    __shared__ float red[512];
    const int b = blockIdx.x, d = threadIdx.x;
    float nrm2 = g_part[b * 512 + d];
    float iv = g_imgf[b * 512 + d];
    red[d] = iv * iv;
    __syncthreads();
    for (int s = 256; s > 0; s >>= 1) {
        if (d < s) red[d] += red[d + s];
        __syncthreads();
    }
    g_h[b * 512 + d] = iv * rsqrtf(red[0]) * rsqrtf(nrm2);
}

__global__ void logits_kernel(const float* __restrict__ ls, float* __restrict__ out)
{
    __shared__ float hs[512];
    const int b = blockIdx.y;
    const int tid = threadIdx.x, warp = tid >> 5, lane = tid & 31;
    const int c = blockIdx.x * 8 + warp;
    for (int i = tid; i < 512; i += 256) hs[i] = g_h[b * 512 + i];
    __syncthreads();
    const __half2* row = (const __half2*)g_txth + ((size_t)b * 1000 + c) * 256;
    float acc = 0.f;
    for (int kk = lane; kk < 256; kk += 32) {
        float2 f = __half22float2(row[kk]);
        acc += hs[kk * 2] * f.x + hs[kk * 2 + 1] * f.y;
    }
    #pragma unroll
    for (int off = 16; off > 0; off >>= 1) acc += __shfl_xor_sync(0xffffffff, acc, off);
    if (lane == 0) out[(size_t)b * 1000 + c] = expf(ls[0]) * acc;
}

// =======================================================================
extern "C" void kernel_launch(void* const* d_in, const int* in_sizes, int n_in,
                              void* d_out, int out_size)
{
    const float* x   = (const float*)d_in[0];
    const float* txt = (const float*)d_in[1];
    const float* siw = (const float*)d_in[2];
    const float* sib = (const float*)d_in[3];
    const float* sow = (const float*)d_in[4];
    const float* sob = (const float*)d_in[5];
    const float* ciw = (const float*)d_in[6];
    const float* cib = (const float*)d_in[7];
    const float* cow = (const float*)d_in[8];
    const float* cob = (const float*)d_in[9];
    const float* ls  = (const float*)d_in[10];
    float* out = (float*)d_out;

    cudaFuncSetAttribute(self_attn_mega, cudaFuncAttributeMaxDynamicSharedMemorySize, 74304);
    cudaFuncSetAttribute(attn_cls_kernel, cudaFuncAttributeMaxDynamicSharedMemorySize, 188928);

    // #1: conversions + cWqT + bqk + g_part zero
    megaconv<<<2224, 256>>>(x, siw, ciw, cow, cib);
    // #2: batched weight GEMMs (qkv | W2 | Wov)
    hgemm3_w<<<416, 256>>>(sib);
    // #3: self-attn + xs + qk + image feature
    self_attn_mega<<<64, 256, 74304>>>(sow, sob);
    // #4: bov
    bov_kernel<<<64, 256>>>(cow, cib, cob);
    // #5: fused cross-attention  <-- ncu capture slot
    attn_cls_kernel<<<1000, 256, 188928>>>(txt);
    // #6-#8
    txt_gemm_kernel<<<dim3(4, 500), 256>>>();
    make_h_kernel<<<64, 512>>>();
    logits_kernel<<<dim3(125, 64), 256>>>(ls, out);
}

// round 13
// speedup vs baseline: 1.5341x; 1.5341x over previous
#include <cuda_runtime.h>
#include <cuda_fp16.h>
#include <cstdint>
#include <mma.h>

using namespace nvcuda;

#define ATTN_SCALE 0.044194173824159216f  // 1/sqrt(512)
#define TH_LD 520
#define SS_LD 100

// ---------------- static device scratch ----------------
__device__ __align__(16) __half g_xhi  [768 * 512],   g_xlo  [768 * 512];
__device__ __align__(16) __half g_siwhi[1536 * 512],  g_siwlo[1536 * 512];
__device__ __align__(16) __half g_sowhi[512 * 512],   g_sowlo[512 * 512];
__device__ __align__(16) __half g_cWkhi[512 * 512],   g_cWklo[512 * 512];
__device__ __align__(16) __half g_cWvhi[512 * 512],   g_cWvlo[512 * 512];
__device__ __align__(16) __half g_cWqThi[512 * 512],  g_cWqTlo[512 * 512];
__device__ __align__(16) __half g_cowhi[512 * 512],   g_cowlo[512 * 512];
__device__ __align__(16) float  g_qkv  [768 * 1536];
__device__ __align__(16) __half g_aohi [768 * 512],   g_aolo [768 * 512];
__device__ __align__(16) float  g_xs   [768 * 512];
__device__ __align__(16) __half g_xshi [768 * 512],   g_xslo [768 * 512];
__device__ __align__(16) __half g_W2hi [512 * 512],   g_W2lo [512 * 512];
__device__ __align__(16) float  g_bqk  [512];
__device__ __align__(16) __half g_qkh  [768 * 512];
__device__ __align__(16) __half g_Wovh [512 * 512];
__device__ __align__(16) float  g_bov  [512];
__device__ __align__(16) __half g_rch  [(size_t)64 * 1000 * 512];
__device__ __align__(16) __half g_txth [(size_t)64 * 1000 * 512];
__device__ __align__(16) float  g_part [64 * 512];
__device__ __align__(16) float  g_h    [64 * 512];

// ---------------- helpers ----------------
__device__ __forceinline__ void cpasync16(uint32_t dst, const void* src) {
    asm volatile("cp.async.cg.shared.global [%0], [%1], 16;"
                 :: "r"(dst), "l"(__cvta_generic_to_global(src)));
}
__device__ __forceinline__ uint32_t smem_u32(const void* p) {
    uint32_t a;
    asm("{ .reg .u64 t; cvta.to.shared.u64 t, %1; cvt.u32.u64 %0, t; }" : "=r"(a) : "l"(p));
    return a;
}
#define CP_COMMIT() asm volatile("cp.async.commit_group;" ::: "memory")
#define CP_WAIT0()  asm volatile("cp.async.wait_group 0;" ::: "memory")

__device__ __forceinline__ void split_f(float x, __half& h, __half& l) {
    h = __float2half(x);
    l = __float2half(x - __half2float(h));
}

// =======================================================================
// MEGA conversion kernel (launch #1): converts + transpose + bqk + bov
// =======================================================================
__global__ void megaconv(const float* __restrict__ x, const float* __restrict__ siw,
                         const float* __restrict__ sow, const float* __restrict__ ciw,
                         const float* __restrict__ cow, const float* __restrict__ cib,
                         const float* __restrict__ cob)
{
    __shared__ float sred[8][33];
    __shared__ float tt[32][33];
    const int blk = blockIdx.x, tid = threadIdx.x;

    if (blk < 2208) {
        const size_t N1 = 98304, N2 = N1 + 196608, N3 = N2 + 65536, N4 = N3 + 65536,
                     N5 = N4 + 65536, N6 = N5 + 65536;
        size_t u = (size_t)blk * 256 + tid;
        if (u >= N6) { ((float4*)g_part)[u - N6] = make_float4(0.f, 0.f, 0.f, 0.f); return; }
        const float* src; __half* hi; __half* lo; size_t o;
        if (u < N1)      { src = x;                hi = g_xhi;   lo = g_xlo;   o = u; }
        else if (u < N2) { src = siw;              hi = g_siwhi; lo = g_siwlo; o = u - N1; }
        else if (u < N3) { src = sow;              hi = g_sowhi; lo = g_sowlo; o = u - N2; }
        else if (u < N4) { src = ciw + 512 * 512;  hi = g_cWkhi; lo = g_cWklo; o = u - N3; }
        else if (u < N5) { src = ciw + 1024 * 512; hi = g_cWvhi; lo = g_cWvlo; o = u - N4; }
        else             { src = cow;              hi = g_cowhi; lo = g_cowlo; o = u - N5; }
        float4 v = ((const float4*)src)[o];
        __half h0, l0, h1, l1, h2, l2, h3, l3;
        split_f(v.x, h0, l0); split_f(v.y, h1, l1);
        split_f(v.z, h2, l2); split_f(v.w, h3, l3);
        __half2* oh = (__half2*)(hi + o * 4);
        __half2* ol = (__half2*)(lo + o * 4);
        oh[0] = __halves2half2(h0, h1); oh[1] = __halves2half2(h2, h3);
        ol[0] = __halves2half2(l0, l1); ol[1] = __halves2half2(l2, l3);
    } else if (blk < 2464) {
        int b = blk - 2208;
        const int tx = tid & 31, ty = tid >> 5;
        const int bx = (b & 15) * 32, by = (b >> 4) * 32;
        #pragma unroll
        for (int j = 0; j < 4; j++)
            tt[ty + j * 8][tx] = ciw[(size_t)(by + ty + j * 8) * 512 + bx + tx];
        __syncthreads();
        #pragma unroll
        for (int j = 0; j < 4; j++) {
            float v = tt[tx][ty + j * 8];
            __half h, l; split_f(v, h, l);
            size_t o = (size_t)(bx + ty + j * 8) * 512 + by + tx;
            g_cWqThi[o] = h; g_cWqTlo[o] = l;
        }
    } else if (blk < 2480) {
        int b = blk - 2464;
        const int dd = tid & 31, eg = tid >> 5;
        const int d = b * 32 + dd;
        const float* cWk = ciw + 512 * 512;
        float s = 0.f;
        const int e0 = eg * 64;
        #pragma unroll 8
        for (int e = e0; e < e0 + 64; e++) s += cib[e] * cWk[(size_t)e * 512 + d];
        sred[eg][dd] = s;
        __syncthreads();
        if (eg == 0) {
            float t = 0.f;
            #pragma unroll
            for (int i = 0; i < 8; i++) t += sred[i][dd];
            g_bqk[d] = t * ATTN_SCALE;
        }
    } else {
        int b = blk - 2480;
        int warp = tid >> 5, lane = tid & 31;
        int i = b * 8 + warp;
        const float* cbv = cib + 1024;
        float s = 0.f;
        for (int e = lane; e < 512; e += 32) s += cow[i * 512 + e] * cbv[e];
        #pragma unroll
        for (int o = 16; o > 0; o >>= 1) s += __shfl_xor_sync(0xffffffff, s, o);
        if (lane == 0) g_bov[i] = s + cob[i];
    }
}

// =======================================================================
// BIG split-fp16 weight GEMM (launch #2): 128x128 tiles, cp.async
// double-buffered, warp tile 64x32. Dispatch:
//   [0,72)   qkv = x @ siw^T + sib  -> g_qkv (f32)
//   [72,88)  W2  = scale*cWqT @ cWk -> g_W2hi/lo
//   [88,104) Wov = cow @ cWv        -> g_Wovh
// dyn smem: 2 bufs x 73728 B; buf: Ahi(18432) Alo(18432) Bhi(18432) Blo(18432)
// K = 512, chunk 64.
// =======================================================================
#define WB_BUF 73728

__global__ void __launch_bounds__(256, 1) hgemm3w_big(const float* __restrict__ sib)
{
    extern __shared__ char ws[];
    const uint32_t sb = smem_u32(ws);
    const int tid = threadIdx.x, warp = tid >> 5;
    const int wr = warp >> 2, wc = warp & 3;   // 2 x 4 warps
    int id = blockIdx.x;

    const __half *Ahi, *Alo, *Bhi, *Blo;
    int bt, m0, n0, N;
    float scale;
    const float* bias;
    float* outF; __half* outHi; __half* outLo;
    if (id < 72) {
        Ahi = g_xhi; Alo = g_xlo; Bhi = g_siwhi; Blo = g_siwlo; bt = 1;
        m0 = (id / 12) * 128; n0 = (id % 12) * 128; N = 1536;
        scale = 1.f; bias = sib; outF = g_qkv; outHi = nullptr; outLo = nullptr;
    } else if (id < 88) {
        id -= 72;
        Ahi = g_cWqThi; Alo = g_cWqTlo; Bhi = g_cWkhi; Blo = g_cWklo; bt = 0;
        m0 = (id / 4) * 128; n0 = (id % 4) * 128; N = 512;
        scale = ATTN_SCALE; bias = nullptr; outF = nullptr; outHi = g_W2hi; outLo = g_W2lo;
    } else {
        id -= 88;
        Ahi = g_cowhi; Alo = g_cowlo; Bhi = g_cWvhi; Blo = g_cWvlo; bt = 0;
        m0 = (id / 4) * 128; n0 = (id % 4) * 128; N = 512;
        scale = 1.f; bias = nullptr; outF = nullptr; outHi = g_Wovh; outLo = nullptr;
    }
    const int K = 512;

    // issue one k-chunk into buffer buf
    auto issue = [&](int kc, int buf) {
        uint32_t base = sb + buf * WB_BUF;
        // A hi/lo: 128 rows x 64 halves = 1024 uint4 each
        #pragma unroll
        for (int it = 0; it < 4; it++) {
            int f = tid + it * 256, r = f >> 3, v = f & 7;
            size_t go = (size_t)(m0 + r) * K + kc * 64 + v * 8;
            cpasync16(base + r * 144 + v * 16,         Ahi + go);
            cpasync16(base + 18432 + r * 144 + v * 16, Alo + go);
        }
        if (bt) {
            #pragma unroll
            for (int it = 0; it < 4; it++) {
                int f = tid + it * 256, r = f >> 3, v = f & 7;
                size_t go = (size_t)(n0 + r) * K + kc * 64 + v * 8;
                cpasync16(base + 36864 + r * 144 + v * 16, Bhi + go);
                cpasync16(base + 55296 + r * 144 + v * 16, Blo + go);
            }
        } else {
            // B[k,n]: 64 k-rows x 128 halves, ld 136 halves (272 B)
            #pragma unroll
            for (int it = 0; it < 4; it++) {
                int f = tid + it * 256, r = f >> 4, v = f & 15;
                size_t go = (size_t)(kc * 64 + r) * N + n0 + v * 8;
                cpasync16(base + 36864 + r * 272 + v * 16, Bhi + go);
                cpasync16(base + 55296 + r * 272 + v * 16, Blo + go);
            }
        }
    };

    wmma::fragment<wmma::accumulator, 16, 16, 16, float> acc[4][2];
    #pragma unroll
    for (int i = 0; i < 4; i++) {
        wmma::fill_fragment(acc[i][0], 0.f);
        wmma::fill_fragment(acc[i][1], 0.f);
    }

    issue(0, 0);
    CP_COMMIT();

    for (int kc = 0; kc < 8; kc++) {
        CP_WAIT0();
        __syncthreads();
        if (kc < 7) { issue(kc + 1, (kc + 1) & 1); CP_COMMIT(); }
        const char* base = ws + (kc & 1) * WB_BUF;
        const __half* Ash = (const __half*)base;
        const __half* Asl = (const __half*)(base + 18432);
        const __half* Bsh = (const __half*)(base + 36864);
        const __half* Bsl = (const __half*)(base + 55296);
        #pragma unroll
        for (int ks = 0; ks < 4; ks++) {
            wmma::fragment<wmma::matrix_a, 16, 16, 16, __half, wmma::row_major> afh[4], afl[4];
            #pragma unroll
            for (int i = 0; i < 4; i++) {
                wmma::load_matrix_sync(afh[i], Ash + ((wr * 64 + i * 16)) * 72 + ks * 16, 72);
                wmma::load_matrix_sync(afl[i], Asl + ((wr * 64 + i * 16)) * 72 + ks * 16, 72);
            }
            #pragma unroll
            for (int j = 0; j < 2; j++) {
                if (bt) {
                    wmma::fragment<wmma::matrix_b, 16, 16, 16, __half, wmma::col_major> bfh, bfl;
                    wmma::load_matrix_sync(bfh, Bsh + ((wc * 32 + j * 16)) * 72 + ks * 16, 72);
                    wmma::load_matrix_sync(bfl, Bsl + ((wc * 32 + j * 16)) * 72 + ks * 16, 72);
                    #pragma unroll
                    for (int i = 0; i < 4; i++) {
                        wmma::mma_sync(acc[i][j], afh[i], bfh, acc[i][j]);
                        wmma::mma_sync(acc[i][j], afh[i], bfl, acc[i][j]);
                        wmma::mma_sync(acc[i][j], afl[i], bfh, acc[i][j]);
                    }
                } else {
                    wmma::fragment<wmma::matrix_b, 16, 16, 16, __half, wmma::row_major> bfh, bfl;
                    wmma::load_matrix_sync(bfh, Bsh + (ks * 16) * 136 + wc * 32 + j * 16, 136);
                    wmma::load_matrix_sync(bfl, Bsl + (ks * 16) * 136 + wc * 32 + j * 16, 136);
                    #pragma unroll
                    for (int i = 0; i < 4; i++) {
                        wmma::mma_sync(acc[i][j], afh[i], bfh, acc[i][j]);
                        wmma::mma_sync(acc[i][j], afh[i], bfl, acc[i][j]);
                        wmma::mma_sync(acc[i][j], afl[i], bfh, acc[i][j]);
                    }
                }
            }
        }
        __syncthreads();
    }

    // epilogue via smem staging (reuse buf0: 128 x 132 f32 = 67584 B)
    float* Cs = (float*)ws;
    #pragma unroll
    for (int i = 0; i < 4; i++)
        #pragma unroll
        for (int j = 0; j < 2; j++)
            wmma::store_matrix_sync(Cs + (size_t)(wr * 64 + i * 16) * 132 + wc * 32 + j * 16,
                                    acc[i][j], 132, wmma::mem_row_major);
    __syncthreads();
    for (int idx = tid; idx < 128 * 128; idx += 256) {
        int r = idx >> 7, n = idx & 127;
        float v = Cs[(size_t)r * 132 + n] * scale + (bias ? bias[n0 + n] : 0.f);
        size_t m = m0 + r;
        if (outF)  outF[m * N + n0 + n] = v;
        if (outHi) {
            __half h = __float2half(v);
            outHi[m * N + n0 + n] = h;
            if (outLo) outLo[m * N + n0 + n] = __float2half(v - __half2float(h));
        }
    }
}

// =======================================================================
// Split-fp16 GEMM 64x64 (xs / qk launches)
// =======================================================================
__global__ void hgemm3(const __half* __restrict__ Ahi, const __half* __restrict__ Alo,
                       const __half* __restrict__ Bhi, const __half* __restrict__ Blo, int bt,
                       const float* __restrict__ bias, float scale,
                       float* __restrict__ Cf, __half* __restrict__ Chi, __half* __restrict__ Clo,
                       int N, int K)
{
    __shared__ __half Ash[64 * 72], Asl[64 * 72];
    __shared__ __half Bsh[64 * 72], Bsl[64 * 72];
    __shared__ float  Cs[64 * 68];
    const int tid = threadIdx.x, warp = tid >> 5;
    const int m0 = blockIdx.y * 64, n0 = blockIdx.x * 64;
    const int wr = warp >> 1, wc = warp & 1;

    wmma::fragment<wmma::accumulator, 16, 16, 16, float> acc[2];
    wmma::fill_fragment(acc[0], 0.f);
    wmma::fill_fragment(acc[1], 0.f);

    uint4 rah[2], ral[2], rbh[2], rbl[2];
    #pragma unroll
    for (int i = 0; i < 2; i++) {
        int f = tid + i * 256, r = f >> 3, v = f & 7;
        rah[i] = ((const uint4*)(Ahi + (size_t)(m0 + r) * K))[v];
        ral[i] = ((const uint4*)(Alo + (size_t)(m0 + r) * K))[v];
        if (bt) {
            rbh[i] = ((const uint4*)(Bhi + (size_t)(n0 + r) * K))[v];
            rbl[i] = ((const uint4*)(Blo + (size_t)(n0 + r) * K))[v];
        } else {
            rbh[i] = ((const uint4*)(Bhi + (size_t)r * N + n0))[v];
            rbl[i] = ((const uint4*)(Blo + (size_t)r * N + n0))[v];
        }
    }
    const int nk = K >> 6;
    for (int kc = 0; kc < nk; kc++) {
        #pragma unroll
        for (int i = 0; i < 2; i++) {
            int f = tid + i * 256, r = f >> 3, v = f & 7;
            *((uint4*)(Ash + r * 72) + v) = rah[i];
            *((uint4*)(Asl + r * 72) + v) = ral[i];
            *((uint4*)(Bsh + r * 72) + v) = rbh[i];
            *((uint4*)(Bsl + r * 72) + v) = rbl[i];
        }
        __syncthreads();
        if (kc + 1 < nk) {
            int kk = (kc + 1) << 6;
            #pragma unroll
            for (int i = 0; i < 2; i++) {
                int f = tid + i * 256, r = f >> 3, v = f & 7;
                rah[i] = ((const uint4*)(Ahi + (size_t)(m0 + r) * K + kk))[v];
                ral[i] = ((const uint4*)(Alo + (size_t)(m0 + r) * K + kk))[v];
                if (bt) {
                    rbh[i] = ((const uint4*)(Bhi + (size_t)(n0 + r) * K + kk))[v];
                    rbl[i] = ((const uint4*)(Blo + (size_t)(n0 + r) * K + kk))[v];
                } else {
                    rbh[i] = ((const uint4*)(Bhi + (size_t)(kk + r) * N + n0))[v];
                    rbl[i] = ((const uint4*)(Blo + (size_t)(kk + r) * N + n0))[v];
                }
            }
        }
        #pragma unroll
        for (int ks = 0; ks < 4; ks++) {
            wmma::fragment<wmma::matrix_a, 16, 16, 16, __half, wmma::row_major> afh, afl;
            wmma::load_matrix_sync(afh, Ash + (wr * 16) * 72 + ks * 16, 72);
            wmma::load_matrix_sync(afl, Asl + (wr * 16) * 72 + ks * 16, 72);
            #pragma unroll
            for (int j = 0; j < 2; j++) {
                if (bt) {
                    wmma::fragment<wmma::matrix_b, 16, 16, 16, __half, wmma::col_major> bfh, bfl;
                    wmma::load_matrix_sync(bfh, Bsh + ((wc * 2 + j) * 16) * 72 + ks * 16, 72);
                    wmma::load_matrix_sync(bfl, Bsl + ((wc * 2 + j) * 16) * 72 + ks * 16, 72);
                    wmma::mma_sync(acc[j], afh, bfh, acc[j]);
                    wmma::mma_sync(acc[j], afh, bfl, acc[j]);
                    wmma::mma_sync(acc[j], afl, bfh, acc[j]);
                } else {
                    wmma::fragment<wmma::matrix_b, 16, 16, 16, __half, wmma::row_major> bfh, bfl;
                    wmma::load_matrix_sync(bfh, Bsh + (ks * 16) * 72 + (wc * 2 + j) * 16, 72);
                    wmma::load_matrix_sync(bfl, Bsl + (ks * 16) * 72 + (wc * 2 + j) * 16, 72);
                    wmma::mma_sync(acc[j], afh, bfh, acc[j]);
                    wmma::mma_sync(acc[j], afh, bfl, acc[j]);
                    wmma::mma_sync(acc[j], afl, bfh, acc[j]);
                }
            }
        }
        __syncthreads();
    }
    wmma::store_matrix_sync(Cs + (wr * 16) * 68 + wc * 32,      acc[0], 68, wmma::mem_row_major);
    wmma::store_matrix_sync(Cs + (wr * 16) * 68 + wc * 32 + 16, acc[1], 68, wmma::mem_row_major);
    __syncthreads();
    for (int i = tid; i < 4096; i += 256) {
        int r = i >> 6, n = i & 63;
        float v = Cs[r * 68 + n] * scale + (bias ? bias[n0 + n] : 0.f);
        size_t m = m0 + r;
        if (Cf)  Cf[m * N + n0 + n] = v;
        if (Chi) {
            __half h = __float2half(v);
            Chi[m * N + n0 + n] = h;
            if (Clo) Clo[m * N + n0 + n] = __float2half(v - __half2float(h));
        }
    }
}

// =======================================================================
// self-attention over the 12-layer axis
// =======================================================================
__global__ void self_attn_kernel()
{
    extern __shared__ float sh[];
    float* q = sh;
    float* k = q + 12 * 512;
    float* v = k + 12 * 512;
    float* S = v + 12 * 512;
    const int b = blockIdx.x, tid = threadIdx.x;
    for (int i = tid; i < 12 * 512; i += 128) {
        int l = i >> 9, d = i & 511;
        const float* row = g_qkv + (size_t)(l * 64 + b) * 1536;
        q[i] = row[d]; k[i] = row[512 + d]; v[i] = row[1024 + d];
    }
    __syncthreads();
    for (int i = tid; i < 144; i += 128) {
        int l = i / 12, m = i - l * 12;
        const float* qp = q + l * 512;
        const float* kp = k + m * 512;
        float s = 0.f;
        for (int e = 0; e < 512; e++) s += qp[e] * kp[e];
        S[i] = s * ATTN_SCALE;
    }
    __syncthreads();
    if (tid < 12) {
        float mx = -1e30f;
        for (int m = 0; m < 12; m++) mx = fmaxf(mx, S[tid * 12 + m]);
        float e[12], sum = 0.f;
        for (int m = 0; m < 12; m++) { e[m] = expf(S[tid * 12 + m] - mx); sum += e[m]; }
        float inv = 1.f / sum;
        for (int m = 0; m < 12; m++) S[tid * 12 + m] = e[m] * inv;
    }
    __syncthreads();
    for (int i = tid; i < 12 * 512; i += 128) {
        int l = i >> 9, d = i & 511;
        float o = 0.f;
        #pragma unroll
        for (int m = 0; m < 12; m++) o += S[l * 12 + m] * v[m * 512 + d];
        __half h, lo; split_f(o, h, lo);
        size_t idx = (size_t)(b * 12 + l) * 512 + d;
        g_aohi[idx] = h; g_aolo[idx] = lo;
    }
}

// =======================================================================
// Fused cross-attention (R7 structure — best measured)
// =======================================================================
#define AQ0 99840
#define AQB 27648
#define WSMOFF 176640

__global__ void attn_cls_kernel(const float* __restrict__ textf)
{
    extern __shared__ char smc[];
    __half* th  = (__half*)smc;
    float*  Ss  = (float*)(smc + AQ0);
    __half* wsm = (__half*)(smc + WSMOFF);
    const uint32_t aqs = smem_u32(smc) + AQ0;
    const int tid  = threadIdx.x;
    const int warp = tid >> 5;
    const int c    = blockIdx.x;
    const int wr = warp >> 1, wc = warp & 1;

    {
        const float4* src = (const float4*)(textf + (size_t)c * (96 * 512));
        for (int i = tid; i < 96 * 128; i += 256) {
            int row = i >> 7, v = i & 127;
            float4 f = src[row * 128 + v];
            __half2* dst = (__half2*)(th + row * TH_LD + v * 4);
            dst[0] = __floats2half2_rn(f.x, f.y);
            dst[1] = __floats2half2_rn(f.z, f.w);
        }
    }
    __syncthreads();

    for (int mch = 0; mch < 4; mch++) {
        const int b0 = mch * 16;
        const __half* qbase = g_qkh + (size_t)(b0 * 12) * 512;

        #pragma unroll
        for (int i = 0; i < 6; i++) {
            int f = tid + i * 256, r = f >> 3, v = f & 7;
            cpasync16(aqs + r * 144 + v * 16, qbase + (size_t)r * 512 + v * 8);
        }
        CP_COMMIT();

        wmma::fragment<wmma::accumulator, 16, 16, 16, float> acc[3][3];
        #pragma unroll
        for (int i = 0; i < 3; i++)
            #pragma unroll
            for (int j = 0; j < 3; j++) wmma::fill_fragment(acc[i][j], 0.f);

        for (int kc = 0; kc < 8; kc++) {
            CP_WAIT0();
            __syncthreads();
            if (kc < 7) {
                uint32_t nbuf = aqs + ((kc + 1) & 1) * AQB;
                #pragma unroll
                for (int i = 0; i < 6; i++) {
                    int f = tid + i * 256, r = f >> 3, v = f & 7;
                    cpasync16(nbuf + r * 144 + v * 16,
                              qbase + (size_t)r * 512 + (kc + 1) * 64 + v * 8);
                }
                CP_COMMIT();
            }
            const __half* aq = (const __half*)(smc + AQ0 + (kc & 1) * AQB);
            #pragma unroll
            for (int ks = 0; ks < 4; ks++) {
                wmma::fragment<wmma::matrix_a, 16, 16, 16, __half, wmma::row_major> af[3];
                #pragma unroll
                for (int i = 0; i < 3; i++)
                    wmma::load_matrix_sync(af[i], aq + ((wr * 3 + i) * 16) * 72 + ks * 16, 72);
                #pragma unroll
                for (int j = 0; j < 3; j++) {
                    wmma::fragment<wmma::matrix_b, 16, 16, 16, __half, wmma::col_major> bf;
                    wmma::load_matrix_sync(bf, th + ((wc * 3 + j) * 16) * TH_LD + kc * 64 + ks * 16, TH_LD);
                    #pragma unroll
                    for (int i = 0; i < 3; i++) wmma::mma_sync(acc[i][j], af[i], bf, acc[i][j]);
                }
            }
        }
        __syncthreads();
        #pragma unroll
        for (int i = 0; i < 3; i++)
            #pragma unroll
            for (int j = 0; j < 3; j++)
                wmma::store_matrix_sync(Ss + ((wr * 3 + i) * 16) * SS_LD + (wc * 3 + j) * 16,
                                        acc[i][j], SS_LD, wmma::mem_row_major);
        __syncthreads();

        if (tid < 128) {
            int bl = tid >> 3, t = tid & 7;
            float wacc[12];
            #pragma unroll
            for (int m = 0; m < 12; m++) wacc[m] = 0.f;
            for (int l = 0; l < 12; l++) {
                int base = (bl * 12 + l) * SS_LD + t;
                float vals[12], mx = -1e30f;
                #pragma unroll
                for (int m = 0; m < 12; m++) { vals[m] = Ss[base + m * 8]; mx = fmaxf(mx, vals[m]); }
                float sum = 0.f;
                #pragma unroll
                for (int m = 0; m < 12; m++) { vals[m] = __expf(vals[m] - mx); sum += vals[m]; }
                float inv = 1.f / sum;
                #pragma unroll
                for (int m = 0; m < 12; m++) wacc[m] += vals[m] * inv;
            }
            #pragma unroll
            for (int m = 0; m < 12; m++)
                wsm[bl * 96 + m * 8 + t] = __float2half(wacc[m] * (1.f / 96.f));
        }
        __syncthreads();

        {
            wmma::fragment<wmma::accumulator, 16, 16, 16, float> rca[4];
            #pragma unroll
            for (int j = 0; j < 4; j++) wmma::fill_fragment(rca[j], 0.f);
            #pragma unroll
            for (int kt = 0; kt < 6; kt++) {
                wmma::fragment<wmma::matrix_a, 16, 16, 16, __half, wmma::row_major> af;
                wmma::load_matrix_sync(af, wsm + kt * 16, 96);
                #pragma unroll
                for (int j = 0; j < 4; j++) {
                    wmma::fragment<wmma::matrix_b, 16, 16, 16, __half, wmma::row_major> bf;
                    wmma::load_matrix_sync(bf, th + (kt * 16) * TH_LD + (warp * 4 + j) * 16, TH_LD);
                    wmma::mma_sync(rca[j], af, bf, rca[j]);
                }
            }
            #pragma unroll
            for (int j = 0; j < 4; j++)
                wmma::store_matrix_sync(Ss + (warp * 4 + j) * 16, rca[j], TH_LD, wmma::mem_row_major);
        }
        __syncthreads();

        for (int i = tid; i < 16 * 512; i += 256) {
            int bl = i >> 9, d = i & 511;
            g_rch[((size_t)(b0 + bl) * 1000 + c) * 512 + d] = __float2half(Ss[bl * TH_LD + d]);
        }
        __syncthreads();
    }
}

// =======================================================================
// txt = rc @ Wov^T + bov -> fp16, fused column-sq-sums. grid (4,500).
// =======================================================================
__global__ void txt_gemm_kernel()
{
    __shared__ __half As[128 * 72];
    __shared__ __half Bs[128 * 72];
    __shared__ float  stg[8][16 * 20];
    __shared__ float  sq[2][128];
    const int tid = threadIdx.x, warp = tid >> 5, lane = tid & 31;
    const size_t m0 = (size_t)blockIdx.y * 128;
    const int n0 = blockIdx.x * 128;
    const int wr = warp >> 1, wc = warp & 1;
    const int b0f = (int)(m0 / 1000);
    uint4 ra[4], rb[4];
    wmma::fragment<wmma::accumulator, 16, 16, 16, float> acc[2][4];
    #pragma unroll
    for (int i = 0; i < 2; i++)
        #pragma unroll
        for (int j = 0; j < 4; j++) wmma::fill_fragment(acc[i][j], 0.f);

    #pragma unroll
    for (int i = 0; i < 4; i++) {
        int f = tid + i * 256, r = f >> 3, v = f & 7;
        ra[i] = ((const uint4*)(g_rch + (m0 + r) * 512))[v];
        rb[i] = ((const uint4*)(g_Wovh + (size_t)(n0 + r) * 512))[v];
    }
    for (int kc = 0; kc < 8; kc++) {
        #pragma unroll
        for (int i = 0; i < 4; i++) {
            int f = tid + i * 256, r = f >> 3, v = f & 7;
            *((uint4*)(As + r * 72) + v) = ra[i];
            *((uint4*)(Bs + r * 72) + v) = rb[i];
        }
        __syncthreads();
        if (kc < 7) {
            int kk = (kc + 1) * 64;
            #pragma unroll
            for (int i = 0; i < 4; i++) {
                int f = tid + i * 256, r = f >> 3, v = f & 7;
                ra[i] = ((const uint4*)(g_rch + (m0 + r) * 512 + kk))[v];
                rb[i] = ((const uint4*)(g_Wovh + (size_t)(n0 + r) * 512 + kk))[v];
            }
        }
        #pragma unroll
        for (int ks = 0; ks < 4; ks++) {
            wmma::fragment<wmma::matrix_a, 16, 16, 16, __half, wmma::row_major> af[2];
            #pragma unroll
            for (int i = 0; i < 2; i++)
                wmma::load_matrix_sync(af[i], As + ((wr * 2 + i) * 16) * 72 + ks * 16, 72);
            #pragma unroll
            for (int j = 0; j < 4; j++) {
                wmma::fragment<wmma::matrix_b, 16, 16, 16, __half, wmma::col_major> bf;
                wmma::load_matrix_sync(bf, Bs + ((wc * 4 + j) * 16) * 72 + ks * 16, 72);
                #pragma unroll
                for (int i = 0; i < 2; i++) wmma::mma_sync(acc[i][j], af[i], bf, acc[i][j]);
            }
        }
        __syncthreads();
    }
    ((float*)sq)[tid] = 0.f;
    __syncthreads();
    float sq0[4] = {0.f, 0.f, 0.f, 0.f};
    float sq1[4] = {0.f, 0.f, 0.f, 0.f};
    #pragma unroll
    for (int i = 0; i < 2; i++)
        #pragma unroll
        for (int j = 0; j < 4; j++) {
            wmma::store_matrix_sync(stg[warp], acc[i][j], 20, wmma::mem_row_major);
            __syncwarp();
            #pragma unroll
            for (int e = 0; e < 8; e++) {
                int f = lane + e * 32, r = f >> 4, cc = f & 15;
                int n = n0 + (wc * 4 + j) * 16 + cc;
                size_t m = m0 + (wr * 2 + i) * 16 + r;
                float v = stg[warp][r * 20 + cc] + g_bov[n];
                g_txth[m * 512 + n] = __float2half(v);
                int bb = (int)(m / 1000) - b0f;
                if (bb == 0) sq0[j] += v * v; else sq1[j] += v * v;
            }
            __syncwarp();
        }
    #pragma unroll
    for (int j = 0; j < 4; j++) {
        int nl = (wc * 4 + j) * 16 + (lane & 15);
        atomicAdd(&sq[0][nl], sq0[j]);
        atomicAdd(&sq[1][nl], sq1[j]);
    }
    __syncthreads();
    if (tid < 128) {
        #pragma unroll
        for (int s = 0; s < 2; s++) {
            int b = b0f + s;
            if (b < 64) atomicAdd(&g_part[b * 512 + n0 + tid], sq[s][tid]);
        }
    }
}

__global__ void make_h_kernel()
{
    __shared__ float red[512];
    const int b = blockIdx.x, d = threadIdx.x;
    float nrm2 = g_part[b * 512 + d];
    float iv = g_xs[(size_t)(b * 12 + 11) * 512 + d];
    red[d] = iv * iv;
    __syncthreads();
    for (int s = 256; s > 0; s >>= 1) {
        if (d < s) red[d] += red[d + s];
        __syncthreads();
    }
    g_h[b * 512 + d] = iv * rsqrtf(red[0]) * rsqrtf(nrm2);
}

__global__ void logits_kernel(const float* __restrict__ ls, float* __restrict__ out)
{
    __shared__ float hs[512];
    const int b = blockIdx.y;
    const int tid = threadIdx.x, warp = tid >> 5, lane = tid & 31;
    const int c = blockIdx.x * 8 + warp;
    for (int i = tid; i < 512; i += 256) hs[i] = g_h[b * 512 + i];
    __syncthreads();
    const __half2* row = (const __half2*)g_txth + ((size_t)b * 1000 + c) * 256;
    float acc = 0.f;
    for (int kk = lane; kk < 256; kk += 32) {
        float2 f = __half22float2(row[kk]);
        acc += hs[kk * 2] * f.x + hs[kk * 2 + 1] * f.y;
    }
    #pragma unroll
    for (int off = 16; off > 0; off >>= 1) acc += __shfl_xor_sync(0xffffffff, acc, off);
    if (lane == 0) out[(size_t)b * 1000 + c] = expf(ls[0]) * acc;
}

// =======================================================================
extern "C" void kernel_launch(void* const* d_in, const int* in_sizes, int n_in,
                              void* d_out, int out_size)
{
    const float* x   = (const float*)d_in[0];
    const float* txt = (const float*)d_in[1];
    const float* siw = (const float*)d_in[2];
    const float* sib = (const float*)d_in[3];
    const float* sow = (const float*)d_in[4];
    const float* sob = (const float*)d_in[5];
    const float* ciw = (const float*)d_in[6];
    const float* cib = (const float*)d_in[7];
    const float* cow = (const float*)d_in[8];
    const float* cob = (const float*)d_in[9];
    const float* ls  = (const float*)d_in[10];
    float* out = (float*)d_out;

    __half *p_aohi, *p_aolo, *p_sowhi, *p_sowlo, *p_xshi, *p_xslo;
    __half *p_W2hi, *p_W2lo, *p_qkh;
    float  *p_xs, *p_bqk;
    cudaGetSymbolAddress((void**)&p_aohi,  g_aohi);
    cudaGetSymbolAddress((void**)&p_aolo,  g_aolo);
    cudaGetSymbolAddress((void**)&p_sowhi, g_sowhi);
    cudaGetSymbolAddress((void**)&p_sowlo, g_sowlo);
    cudaGetSymbolAddress((void**)&p_xshi,  g_xshi);
    cudaGetSymbolAddress((void**)&p_xslo,  g_xslo);
    cudaGetSymbolAddress((void**)&p_W2hi,  g_W2hi);
    cudaGetSymbolAddress((void**)&p_W2lo,  g_W2lo);
    cudaGetSymbolAddress((void**)&p_qkh,   g_qkh);
    cudaGetSymbolAddress((void**)&p_xs,    g_xs);
    cudaGetSymbolAddress((void**)&p_bqk,   g_bqk);

    cudaFuncSetAttribute(self_attn_kernel, cudaFuncAttributeMaxDynamicSharedMemorySize, 74304);
    cudaFuncSetAttribute(attn_cls_kernel,  cudaFuncAttributeMaxDynamicSharedMemorySize, 188928);
    cudaFuncSetAttribute(hgemm3w_big,      cudaFuncAttributeMaxDynamicSharedMemorySize, 2 * WB_BUF);

    // #1: conversions + cWqT + bqk + bov + g_part zero
    megaconv<<<2544, 256>>>(x, siw, sow, ciw, cow, cib, cob);
    // #2: batched weight GEMMs, 128x128 tiles (qkv | W2 | Wov)
    hgemm3w_big<<<104, 256, 2 * WB_BUF>>>(sib);
    // #3: self-attention
    self_attn_kernel<<<64, 128, 74304>>>();
    // #4: xs = ao @ sow^T + sob
    hgemm3<<<dim3(8, 12), 256>>>(p_aohi, p_aolo, p_sowhi, p_sowlo, 1, sob, 1.f,
                                 p_xs, p_xshi, p_xslo, 512, 512);
    // #5: qk = xs @ W2 + bqk
    hgemm3<<<dim3(8, 12), 256>>>(p_xshi, p_xslo, p_W2hi, p_W2lo, 0, p_bqk, 1.f,
                                 nullptr, p_qkh, nullptr, 512, 512);
    // #6: fused cross-attention
    attn_cls_kernel<<<1000, 256, 188928>>>(txt);
    // #7-#9
    txt_gemm_kernel<<<dim3(4, 500), 256>>>();
    make_h_kernel<<<64, 512>>>();
    logits_kernel<<<dim3(125, 64), 256>>>(ls, out);
}

// round 14
// speedup vs baseline: 1.6022x; 1.0444x over previous
#include <cuda_runtime.h>
#include <cuda_fp16.h>
#include <cstdint>
#include <mma.h>

using namespace nvcuda;

#define ATTN_SCALE 0.044194173824159216f  // 1/sqrt(512)
#define TH_LD 520
#define SS_LD 100
#define WLD   104

// ---------------- static device scratch ----------------
__device__ __align__(16) __half g_xhi  [768 * 512],   g_xlo  [768 * 512];
__device__ __align__(16) __half g_siwhi[1536 * 512],  g_siwlo[1536 * 512];
__device__ __align__(16) __half g_sowhi[512 * 512],   g_sowlo[512 * 512];
__device__ __align__(16) __half g_cWkhi[512 * 512],   g_cWklo[512 * 512];
__device__ __align__(16) __half g_cWvhi[512 * 512],   g_cWvlo[512 * 512];
__device__ __align__(16) __half g_cWqThi[512 * 512],  g_cWqTlo[512 * 512];
__device__ __align__(16) __half g_cowhi[512 * 512],   g_cowlo[512 * 512];
__device__ __align__(16) float  g_qkv  [768 * 1536];
__device__ __align__(16) __half g_aohi [768 * 512],   g_aolo [768 * 512];
__device__ __align__(16) float  g_xs   [768 * 512];
__device__ __align__(16) __half g_xshi [768 * 512],   g_xslo [768 * 512];
__device__ __align__(16) __half g_W2hi [512 * 512],   g_W2lo [512 * 512];
__device__ __align__(16) float  g_bqk  [512];
__device__ __align__(16) __half g_qkh  [768 * 512];
__device__ __align__(16) __half g_Wovh [512 * 512];
__device__ __align__(16) float  g_bov  [512];
__device__ __align__(16) __half g_texth[(size_t)1000 * 96 * 512];
__device__ __align__(16) __half g_w    [(size_t)1000 * 64 * 96];
__device__ __align__(16) __half g_rch  [(size_t)64 * 1000 * 512];
__device__ __align__(16) __half g_txth [(size_t)64 * 1000 * 512];
__device__ __align__(16) float  g_part [64 * 512];
__device__ __align__(16) float  g_h    [64 * 512];

// ---------------- helpers ----------------
__device__ __forceinline__ void cpasync16(uint32_t dst, const void* src) {
    asm volatile("cp.async.cg.shared.global [%0], [%1], 16;"
                 :: "r"(dst), "l"(__cvta_generic_to_global(src)));
}
__device__ __forceinline__ uint32_t smem_u32(const void* p) {
    uint32_t a;
    asm("{ .reg .u64 t; cvta.to.shared.u64 t, %1; cvt.u32.u64 %0, t; }" : "=r"(a) : "l"(p));
    return a;
}
#define CP_COMMIT() asm volatile("cp.async.commit_group;" ::: "memory")
#define CP_WAIT0()  asm volatile("cp.async.wait_group 0;" ::: "memory")

__device__ __forceinline__ void split_f(float x, __half& h, __half& l) {
    h = __float2half(x);
    l = __float2half(x - __half2float(h));
}

// text fp32 -> fp16 (single)
__global__ void f2h_text(const float* __restrict__ in)
{
    size_t i = ((size_t)blockIdx.x * 256 + threadIdx.x) * 4;
    float4 v = *(const float4*)(in + i);
    __half2* o = (__half2*)(g_texth + i);
    o[0] = __floats2half2_rn(v.x, v.y);
    o[1] = __floats2half2_rn(v.z, v.w);
}

// =======================================================================
// MEGA conversion kernel: converts + transpose + bqk + bov (R10 version)
// =======================================================================
__global__ void megaconv(const float* __restrict__ x, const float* __restrict__ siw,
                         const float* __restrict__ sow, const float* __restrict__ ciw,
                         const float* __restrict__ cow, const float* __restrict__ cib,
                         const float* __restrict__ cob)
{
    __shared__ float sred[8][33];
    __shared__ float tt[32][33];
    const int blk = blockIdx.x, tid = threadIdx.x;

    if (blk < 2208) {
        const size_t N1 = 98304, N2 = N1 + 196608, N3 = N2 + 65536, N4 = N3 + 65536,
                     N5 = N4 + 65536, N6 = N5 + 65536;
        size_t u = (size_t)blk * 256 + tid;
        if (u >= N6) { ((float4*)g_part)[u - N6] = make_float4(0.f, 0.f, 0.f, 0.f); return; }
        const float* src; __half* hi; __half* lo; size_t o;
        if (u < N1)      { src = x;                hi = g_xhi;   lo = g_xlo;   o = u; }
        else if (u < N2) { src = siw;              hi = g_siwhi; lo = g_siwlo; o = u - N1; }
        else if (u < N3) { src = sow;              hi = g_sowhi; lo = g_sowlo; o = u - N2; }
        else if (u < N4) { src = ciw + 512 * 512;  hi = g_cWkhi; lo = g_cWklo; o = u - N3; }
        else if (u < N5) { src = ciw + 1024 * 512; hi = g_cWvhi; lo = g_cWvlo; o = u - N4; }
        else             { src = cow;              hi = g_cowhi; lo = g_cowlo; o = u - N5; }
        float4 v = ((const float4*)src)[o];
        __half h0, l0, h1, l1, h2, l2, h3, l3;
        split_f(v.x, h0, l0); split_f(v.y, h1, l1);
        split_f(v.z, h2, l2); split_f(v.w, h3, l3);
        __half2* oh = (__half2*)(hi + o * 4);
        __half2* ol = (__half2*)(lo + o * 4);
        oh[0] = __halves2half2(h0, h1); oh[1] = __halves2half2(h2, h3);
        ol[0] = __halves2half2(l0, l1); ol[1] = __halves2half2(l2, l3);
    } else if (blk < 2464) {
        int b = blk - 2208;
        const int tx = tid & 31, ty = tid >> 5;
        const int bx = (b & 15) * 32, by = (b >> 4) * 32;
        #pragma unroll
        for (int j = 0; j < 4; j++)
            tt[ty + j * 8][tx] = ciw[(size_t)(by + ty + j * 8) * 512 + bx + tx];
        __syncthreads();
        #pragma unroll
        for (int j = 0; j < 4; j++) {
            float v = tt[tx][ty + j * 8];
            __half h, l; split_f(v, h, l);
            size_t o = (size_t)(bx + ty + j * 8) * 512 + by + tx;
            g_cWqThi[o] = h; g_cWqTlo[o] = l;
        }
    } else if (blk < 2480) {
        int b = blk - 2464;
        const int dd = tid & 31, eg = tid >> 5;
        const int d = b * 32 + dd;
        const float* cWk = ciw + 512 * 512;
        float s = 0.f;
        const int e0 = eg * 64;
        #pragma unroll 8
        for (int e = e0; e < e0 + 64; e++) s += cib[e] * cWk[(size_t)e * 512 + d];
        sred[eg][dd] = s;
        __syncthreads();
        if (eg == 0) {
            float t = 0.f;
            #pragma unroll
            for (int i = 0; i < 8; i++) t += sred[i][dd];
            g_bqk[d] = t * ATTN_SCALE;
        }
    } else {
        int b = blk - 2480;
        int warp = tid >> 5, lane = tid & 31;
        int i = b * 8 + warp;
        const float* cbv = cib + 1024;
        float s = 0.f;
        for (int e = lane; e < 512; e += 32) s += cow[i * 512 + e] * cbv[e];
        #pragma unroll
        for (int o = 16; o > 0; o >>= 1) s += __shfl_xor_sync(0xffffffff, s, o);
        if (lane == 0) g_bov[i] = s + cob[i];
    }
}

// =======================================================================
// Split-fp16 GEMM body
// =======================================================================
__device__ __forceinline__ void hg3_body(
    __half* Ash, __half* Asl, __half* Bsh, __half* Bsl, float* Cs,
    const __half* __restrict__ Ahi, const __half* __restrict__ Alo,
    const __half* __restrict__ Bhi, const __half* __restrict__ Blo, int bt,
    const float* __restrict__ bias, float scale,
    float* __restrict__ Cf, __half* __restrict__ Chi, __half* __restrict__ Clo,
    int N, int K, int m0, int n0)
{
    const int tid = threadIdx.x, warp = tid >> 5;
    const int wr = warp >> 1, wc = warp & 1;

    wmma::fragment<wmma::accumulator, 16, 16, 16, float> acc[2];
    wmma::fill_fragment(acc[0], 0.f);
    wmma::fill_fragment(acc[1], 0.f);

    uint4 rah[2], ral[2], rbh[2], rbl[2];
    #pragma unroll
    for (int i = 0; i < 2; i++) {
        int f = tid + i * 256, r = f >> 3, v = f & 7;
        rah[i] = ((const uint4*)(Ahi + (size_t)(m0 + r) * K))[v];
        ral[i] = ((const uint4*)(Alo + (size_t)(m0 + r) * K))[v];
        if (bt) {
            rbh[i] = ((const uint4*)(Bhi + (size_t)(n0 + r) * K))[v];
            rbl[i] = ((const uint4*)(Blo + (size_t)(n0 + r) * K))[v];
        } else {
            rbh[i] = ((const uint4*)(Bhi + (size_t)r * N + n0))[v];
            rbl[i] = ((const uint4*)(Blo + (size_t)r * N + n0))[v];
        }
    }
    const int nk = K >> 6;
    for (int kc = 0; kc < nk; kc++) {
        #pragma unroll
        for (int i = 0; i < 2; i++) {
            int f = tid + i * 256, r = f >> 3, v = f & 7;
            *((uint4*)(Ash + r * 72) + v) = rah[i];
            *((uint4*)(Asl + r * 72) + v) = ral[i];
            *((uint4*)(Bsh + r * 72) + v) = rbh[i];
            *((uint4*)(Bsl + r * 72) + v) = rbl[i];
        }
        __syncthreads();
        if (kc + 1 < nk) {
            int kk = (kc + 1) << 6;
            #pragma unroll
            for (int i = 0; i < 2; i++) {
                int f = tid + i * 256, r = f >> 3, v = f & 7;
                rah[i] = ((const uint4*)(Ahi + (size_t)(m0 + r) * K + kk))[v];
                ral[i] = ((const uint4*)(Alo + (size_t)(m0 + r) * K + kk))[v];
                if (bt) {
                    rbh[i] = ((const uint4*)(Bhi + (size_t)(n0 + r) * K + kk))[v];
                    rbl[i] = ((const uint4*)(Blo + (size_t)(n0 + r) * K + kk))[v];
                } else {
                    rbh[i] = ((const uint4*)(Bhi + (size_t)(kk + r) * N + n0))[v];
                    rbl[i] = ((const uint4*)(Blo + (size_t)(kk + r) * N + n0))[v];
                }
            }
        }
        #pragma unroll
        for (int ks = 0; ks < 4; ks++) {
            wmma::fragment<wmma::matrix_a, 16, 16, 16, __half, wmma::row_major> afh, afl;
            wmma::load_matrix_sync(afh, Ash + (wr * 16) * 72 + ks * 16, 72);
            wmma::load_matrix_sync(afl, Asl + (wr * 16) * 72 + ks * 16, 72);
            #pragma unroll
            for (int j = 0; j < 2; j++) {
                if (bt) {
                    wmma::fragment<wmma::matrix_b, 16, 16, 16, __half, wmma::col_major> bfh, bfl;
                    wmma::load_matrix_sync(bfh, Bsh + ((wc * 2 + j) * 16) * 72 + ks * 16, 72);
                    wmma::load_matrix_sync(bfl, Bsl + ((wc * 2 + j) * 16) * 72 + ks * 16, 72);
                    wmma::mma_sync(acc[j], afh, bfh, acc[j]);
                    wmma::mma_sync(acc[j], afh, bfl, acc[j]);
                    wmma::mma_sync(acc[j], afl, bfh, acc[j]);
                } else {
                    wmma::fragment<wmma::matrix_b, 16, 16, 16, __half, wmma::row_major> bfh, bfl;
                    wmma::load_matrix_sync(bfh, Bsh + (ks * 16) * 72 + (wc * 2 + j) * 16, 72);
                    wmma::load_matrix_sync(bfl, Bsl + (ks * 16) * 72 + (wc * 2 + j) * 16, 72);
                    wmma::mma_sync(acc[j], afh, bfh, acc[j]);
                    wmma::mma_sync(acc[j], afh, bfl, acc[j]);
                    wmma::mma_sync(acc[j], afl, bfh, acc[j]);
                }
            }
        }
        __syncthreads();
    }
    wmma::store_matrix_sync(Cs + (wr * 16) * 68 + wc * 32,      acc[0], 68, wmma::mem_row_major);
    wmma::store_matrix_sync(Cs + (wr * 16) * 68 + wc * 32 + 16, acc[1], 68, wmma::mem_row_major);
    __syncthreads();
    for (int i = tid; i < 4096; i += 256) {
        int r = i >> 6, n = i & 63;
        float v = Cs[r * 68 + n] * scale + (bias ? bias[n0 + n] : 0.f);
        size_t m = m0 + r;
        if (Cf)  Cf[m * N + n0 + n] = v;
        if (Chi) {
            __half h = __float2half(v);
            Chi[m * N + n0 + n] = h;
            if (Clo) Clo[m * N + n0 + n] = __float2half(v - __half2float(h));
        }
    }
}

__global__ void hgemm3(const __half* Ahi, const __half* Alo,
                       const __half* Bhi, const __half* Blo, int bt,
                       const float* bias, float scale,
                       float* Cf, __half* Chi, __half* Clo, int N, int K)
{
    __shared__ __half Ash[64 * 72], Asl[64 * 72], Bsh[64 * 72], Bsl[64 * 72];
    __shared__ float  Cs[64 * 68];
    hg3_body(Ash, Asl, Bsh, Bsl, Cs, Ahi, Alo, Bhi, Blo, bt, bias, scale,
             Cf, Chi, Clo, N, K, blockIdx.y * 64, blockIdx.x * 64);
}

__global__ void hgemm3_w(const float* __restrict__ sib)
{
    __shared__ __half Ash[64 * 72], Asl[64 * 72], Bsh[64 * 72], Bsl[64 * 72];
    __shared__ float  Cs[64 * 68];
    int id = blockIdx.x;
    if (id < 288) {
        hg3_body(Ash, Asl, Bsh, Bsl, Cs, g_xhi, g_xlo, g_siwhi, g_siwlo, 1, sib, 1.f,
                 g_qkv, nullptr, nullptr, 1536, 512, (id / 24) * 64, (id % 24) * 64);
    } else if (id < 352) {
        id -= 288;
        hg3_body(Ash, Asl, Bsh, Bsl, Cs, g_cWqThi, g_cWqTlo, g_cWkhi, g_cWklo, 0, nullptr,
                 ATTN_SCALE, nullptr, g_W2hi, g_W2lo, 512, 512, (id / 8) * 64, (id % 8) * 64);
    } else {
        id -= 352;
        hg3_body(Ash, Asl, Bsh, Bsl, Cs, g_cowhi, g_cowlo, g_cWvhi, g_cWvlo, 0, nullptr,
                 1.f, nullptr, g_Wovh, nullptr, 512, 512, (id / 8) * 64, (id % 8) * 64);
    }
}

// =======================================================================
// self-attention
// =======================================================================
__global__ void self_attn_kernel()
{
    extern __shared__ float sh[];
    float* q = sh;
    float* k = q + 12 * 512;
    float* v = k + 12 * 512;
    float* S = v + 12 * 512;
    const int b = blockIdx.x, tid = threadIdx.x;
    for (int i = tid; i < 12 * 512; i += 128) {
        int l = i >> 9, d = i & 511;
        const float* row = g_qkv + (size_t)(l * 64 + b) * 1536;
        q[i] = row[d]; k[i] = row[512 + d]; v[i] = row[1024 + d];
    }
    __syncthreads();
    for (int i = tid; i < 144; i += 128) {
        int l = i / 12, m = i - l * 12;
        const float* qp = q + l * 512;
        const float* kp = k + m * 512;
        float s = 0.f;
        for (int e = 0; e < 512; e++) s += qp[e] * kp[e];
        S[i] = s * ATTN_SCALE;
    }
    __syncthreads();
    if (tid < 12) {
        float mx = -1e30f;
        for (int m = 0; m < 12; m++) mx = fmaxf(mx, S[tid * 12 + m]);
        float e[12], sum = 0.f;
        for (int m = 0; m < 12; m++) { e[m] = expf(S[tid * 12 + m] - mx); sum += e[m]; }
        float inv = 1.f / sum;
        for (int m = 0; m < 12; m++) S[tid * 12 + m] = e[m] * inv;
    }
    __syncthreads();
    for (int i = tid; i < 12 * 512; i += 128) {
        int l = i >> 9, d = i & 511;
        float o = 0.f;
        #pragma unroll
        for (int m = 0; m < 12; m++) o += S[l * 12 + m] * v[m * 512 + d];
        __half h, lo; split_f(o, h, lo);
        size_t idx = (size_t)(b * 12 + l) * 512 + d;
        g_aohi[idx] = h; g_aolo[idx] = lo;
    }
}

// =======================================================================
// S-kernel: stream q AND text k-chunks, 2 CTAs/SM. grid 1000 x 256 thr.
// smem: aq 2x27648 at 0 | th 2x13824 at 55296 | total 82944
// Ss overlays at 0 after mainloop (192x100 f32 = 76800).
// Writes softmax-layer-summed weights to g_w [c][64][96] fp16.
// =======================================================================
#define SAQ 0
#define STH 55296

__global__ void __launch_bounds__(256, 2) attn_cls_s()
{
    extern __shared__ char smc[];
    const uint32_t sb = smem_u32(smc);
    float* Ss = (float*)smc;
    const int tid  = threadIdx.x;
    const int warp = tid >> 5;
    const int c    = blockIdx.x;
    const int wr = warp >> 1, wc = warp & 1;
    const __half* tbase = g_texth + (size_t)c * 96 * 512;

    for (int mch = 0; mch < 4; mch++) {
        const __half* qbase = g_qkh + (size_t)(mch * 192) * 512;

        // issue chunk 0
        #pragma unroll
        for (int i = 0; i < 6; i++) {
            int f = tid + i * 256, r = f >> 3, v = f & 7;
            cpasync16(sb + SAQ + r * 144 + v * 16, qbase + (size_t)r * 512 + v * 8);
        }
        #pragma unroll
        for (int i = 0; i < 3; i++) {
            int f = tid + i * 256, r = f >> 3, v = f & 7;
            cpasync16(sb + STH + r * 144 + v * 16, tbase + (size_t)r * 512 + v * 8);
        }
        CP_COMMIT();

        wmma::fragment<wmma::accumulator, 16, 16, 16, float> acc[3][3];
        #pragma unroll
        for (int i = 0; i < 3; i++)
            #pragma unroll
            for (int j = 0; j < 3; j++) wmma::fill_fragment(acc[i][j], 0.f);

        for (int kc = 0; kc < 8; kc++) {
            CP_WAIT0();
            __syncthreads();
            if (kc < 7) {
                int nb = (kc + 1) & 1;
                int kk = (kc + 1) * 64;
                #pragma unroll
                for (int i = 0; i < 6; i++) {
                    int f = tid + i * 256, r = f >> 3, v = f & 7;
                    cpasync16(sb + SAQ + nb * 27648 + r * 144 + v * 16,
                              qbase + (size_t)r * 512 + kk + v * 8);
                }
                #pragma unroll
                for (int i = 0; i < 3; i++) {
                    int f = tid + i * 256, r = f >> 3, v = f & 7;
                    cpasync16(sb + STH + nb * 13824 + r * 144 + v * 16,
                              tbase + (size_t)r * 512 + kk + v * 8);
                }
                CP_COMMIT();
            }
            const __half* aq = (const __half*)(smc + SAQ + (kc & 1) * 27648);
            const __half* th = (const __half*)(smc + STH + (kc & 1) * 13824);
            #pragma unroll
            for (int ks = 0; ks < 4; ks++) {
                wmma::fragment<wmma::matrix_a, 16, 16, 16, __half, wmma::row_major> af[3];
                #pragma unroll
                for (int i = 0; i < 3; i++)
                    wmma::load_matrix_sync(af[i], aq + ((wr * 3 + i) * 16) * 72 + ks * 16, 72);
                #pragma unroll
                for (int j = 0; j < 3; j++) {
                    wmma::fragment<wmma::matrix_b, 16, 16, 16, __half, wmma::col_major> bf;
                    wmma::load_matrix_sync(bf, th + ((wc * 3 + j) * 16) * 72 + ks * 16, 72);
                    #pragma unroll
                    for (int i = 0; i < 3; i++) wmma::mma_sync(acc[i][j], af[i], bf, acc[i][j]);
                }
            }
        }
        __syncthreads();   // mainloop done; buffers free for Ss
        #pragma unroll
        for (int i = 0; i < 3; i++)
            #pragma unroll
            for (int j = 0; j < 3; j++)
                wmma::store_matrix_sync(Ss + ((wr * 3 + i) * 16) * SS_LD + (wc * 3 + j) * 16,
                                        acc[i][j], SS_LD, wmma::mem_row_major);
        __syncthreads();

        // softmax over m, sum over l, /96 -> g_w directly
        if (tid < 128) {
            int bl = tid >> 3, t = tid & 7;
            float wacc[12];
            #pragma unroll
            for (int m = 0; m < 12; m++) wacc[m] = 0.f;
            for (int l = 0; l < 12; l++) {
                int base = (bl * 12 + l) * SS_LD + t;
                float vals[12], mx = -1e30f;
                #pragma unroll
                for (int m = 0; m < 12; m++) { vals[m] = Ss[base + m * 8]; mx = fmaxf(mx, vals[m]); }
                float sum = 0.f;
                #pragma unroll
                for (int m = 0; m < 12; m++) { vals[m] = __expf(vals[m] - mx); sum += vals[m]; }
                float inv = 1.f / sum;
                #pragma unroll
                for (int m = 0; m < 12; m++) wacc[m] += vals[m] * inv;
            }
            __half* wrow = g_w + ((size_t)c * 64 + mch * 16 + bl) * 96;
            #pragma unroll
            for (int m = 0; m < 12; m++)
                wrow[m * 8 + t] = __float2half(wacc[m] * (1.f / 96.f));
        }
        __syncthreads();   // Ss reads done before next mch's cp.async overwrites
    }
}

// =======================================================================
// rc = w @ text per class. grid 1000, 256 thr. dyn smem 123392.
// =======================================================================
__global__ void rc_kernel()
{
    extern __shared__ char sm[];
    __half* th = (__half*)sm;                       // 96 x TH_LD
    __half* ws = (__half*)(sm + 99840);             // 64 x WLD
    float*  stg = (float*)(sm + 99840 + 13312);     // 8 x 320
    const int tid = threadIdx.x, warp = tid >> 5, lane = tid & 31;
    const int c = blockIdx.x;

    const __half* tsrc = g_texth + (size_t)c * 96 * 512;
    for (int i = tid; i < 96 * 64; i += 256) {
        int p = i >> 6, v = i & 63;
        *((uint4*)(th + p * TH_LD) + v) = ((const uint4*)(tsrc + (size_t)p * 512))[v];
    }
    for (int i = tid; i < 768; i += 256) {
        int r = i / 12, v = i - r * 12;
        *((uint4*)(ws + r * WLD) + v) = ((const uint4*)(g_w + ((size_t)c * 64 + r) * 96))[v];
    }
    __syncthreads();

    const int n0w = warp * 64;
    wmma::fragment<wmma::accumulator, 16, 16, 16, float> acc[4][4];
    #pragma unroll
    for (int i = 0; i < 4; i++)
        #pragma unroll
        for (int j = 0; j < 4; j++) wmma::fill_fragment(acc[i][j], 0.f);
    #pragma unroll
    for (int kt = 0; kt < 6; kt++) {
        wmma::fragment<wmma::matrix_a, 16, 16, 16, __half, wmma::row_major> af[4];
        #pragma unroll
        for (int i = 0; i < 4; i++)
            wmma::load_matrix_sync(af[i], ws + (i * 16) * WLD + kt * 16, WLD);
        #pragma unroll
        for (int j = 0; j < 4; j++) {
            wmma::fragment<wmma::matrix_b, 16, 16, 16, __half, wmma::row_major> bf;
            wmma::load_matrix_sync(bf, th + (kt * 16) * TH_LD + n0w + j * 16, TH_LD);
            #pragma unroll
            for (int i = 0; i < 4; i++) wmma::mma_sync(acc[i][j], af[i], bf, acc[i][j]);
        }
    }
    float* mystg = stg + warp * 320;
    #pragma unroll
    for (int i = 0; i < 4; i++)
        #pragma unroll
        for (int j = 0; j < 4; j++) {
            wmma::store_matrix_sync(mystg, acc[i][j], 20, wmma::mem_row_major);
            __syncwarp();
            #pragma unroll
            for (int e = 0; e < 8; e++) {
                int f = lane + e * 32, r = f >> 4, cc = f & 15;
                g_rch[((size_t)(i * 16 + r) * 1000 + c) * 512 + n0w + j * 16 + cc] =
                    __float2half(mystg[r * 20 + cc]);
            }
            __syncwarp();
        }
}

// =======================================================================
// txt = rc @ Wov^T + bov -> fp16, fused column-sq-sums. grid (4,500).
// =======================================================================
__global__ void txt_gemm_kernel()
{
    __shared__ __half As[128 * 72];
    __shared__ __half Bs[128 * 72];
    __shared__ float  stg[8][16 * 20];
    __shared__ float  sq[2][128];
    const int tid = threadIdx.x, warp = tid >> 5, lane = tid & 31;
    const size_t m0 = (size_t)blockIdx.y * 128;
    const int n0 = blockIdx.x * 128;
    const int wr = warp >> 1, wc = warp & 1;
    const int b0f = (int)(m0 / 1000);
    uint4 ra[4], rb[4];
    wmma::fragment<wmma::accumulator, 16, 16, 16, float> acc[2][4];
    #pragma unroll
    for (int i = 0; i < 2; i++)
        #pragma unroll
        for (int j = 0; j < 4; j++) wmma::fill_fragment(acc[i][j], 0.f);

    #pragma unroll
    for (int i = 0; i < 4; i++) {
        int f = tid + i * 256, r = f >> 3, v = f & 7;
        ra[i] = ((const uint4*)(g_rch + (m0 + r) * 512))[v];
        rb[i] = ((const uint4*)(g_Wovh + (size_t)(n0 + r) * 512))[v];
    }
    for (int kc = 0; kc < 8; kc++) {
        #pragma unroll
        for (int i = 0; i < 4; i++) {
            int f = tid + i * 256, r = f >> 3, v = f & 7;
            *((uint4*)(As + r * 72) + v) = ra[i];
            *((uint4*)(Bs + r * 72) + v) = rb[i];
        }
        __syncthreads();
        if (kc < 7) {
            int kk = (kc + 1) * 64;
            #pragma unroll
            for (int i = 0; i < 4; i++) {
                int f = tid + i * 256, r = f >> 3, v = f & 7;
                ra[i] = ((const uint4*)(g_rch + (m0 + r) * 512 + kk))[v];
                rb[i] = ((const uint4*)(g_Wovh + (size_t)(n0 + r) * 512 + kk))[v];
            }
        }
        #pragma unroll
        for (int ks = 0; ks < 4; ks++) {
            wmma::fragment<wmma::matrix_a, 16, 16, 16, __half, wmma::row_major> af[2];
            #pragma unroll
            for (int i = 0; i < 2; i++)
                wmma::load_matrix_sync(af[i], As + ((wr * 2 + i) * 16) * 72 + ks * 16, 72);
            #pragma unroll
            for (int j = 0; j < 4; j++) {
                wmma::fragment<wmma::matrix_b, 16, 16, 16, __half, wmma::col_major> bf;
                wmma::load_matrix_sync(bf, Bs + ((wc * 4 + j) * 16) * 72 + ks * 16, 72);
                #pragma unroll
                for (int i = 0; i < 2; i++) wmma::mma_sync(acc[i][j], af[i], bf, acc[i][j]);
            }
        }
        __syncthreads();
    }
    ((float*)sq)[tid] = 0.f;
    __syncthreads();
    float sq0[4] = {0.f, 0.f, 0.f, 0.f};
    float sq1[4] = {0.f, 0.f, 0.f, 0.f};
    #pragma unroll
    for (int i = 0; i < 2; i++)
        #pragma unroll
        for (int j = 0; j < 4; j++) {
            wmma::store_matrix_sync(stg[warp], acc[i][j], 20, wmma::mem_row_major);
            __syncwarp();
            #pragma unroll
            for (int e = 0; e < 8; e++) {
                int f = lane + e * 32, r = f >> 4, cc = f & 15;
                int n = n0 + (wc * 4 + j) * 16 + cc;
                size_t m = m0 + (wr * 2 + i) * 16 + r;
                float v = stg[warp][r * 20 + cc] + g_bov[n];
                g_txth[m * 512 + n] = __float2half(v);
                int bb = (int)(m / 1000) - b0f;
                if (bb == 0) sq0[j] += v * v; else sq1[j] += v * v;
            }
            __syncwarp();
        }
    #pragma unroll
    for (int j = 0; j < 4; j++) {
        int nl = (wc * 4 + j) * 16 + (lane & 15);
        atomicAdd(&sq[0][nl], sq0[j]);
        atomicAdd(&sq[1][nl], sq1[j]);
    }
    __syncthreads();
    if (tid < 128) {
        #pragma unroll
        for (int s = 0; s < 2; s++) {
            int b = b0f + s;
            if (b < 64) atomicAdd(&g_part[b * 512 + n0 + tid], sq[s][tid]);
        }
    }
}

__global__ void make_h_kernel()
{
    __shared__ float red[512];
    const int b = blockIdx.x, d = threadIdx.x;
    float nrm2 = g_part[b * 512 + d];
    float iv = g_xs[(size_t)(b * 12 + 11) * 512 + d];
    red[d] = iv * iv;
    __syncthreads();
    for (int s = 256; s > 0; s >>= 1) {
        if (d < s) red[d] += red[d + s];
        __syncthreads();
    }
    g_h[b * 512 + d] = iv * rsqrtf(red[0]) * rsqrtf(nrm2);
}

__global__ void logits_kernel(const float* __restrict__ ls, float* __restrict__ out)
{
    __shared__ float hs[512];
    const int b = blockIdx.y;
    const int tid = threadIdx.x, warp = tid >> 5, lane = tid & 31;
    const int c = blockIdx.x * 8 + warp;
    for (int i = tid; i < 512; i += 256) hs[i] = g_h[b * 512 + i];
    __syncthreads();
    const __half2* row = (const __half2*)g_txth + ((size_t)b * 1000 + c) * 256;
    float acc = 0.f;
    for (int kk = lane; kk < 256; kk += 32) {
        float2 f = __half22float2(row[kk]);
        acc += hs[kk * 2] * f.x + hs[kk * 2 + 1] * f.y;
    }
    #pragma unroll
    for (int off = 16; off > 0; off >>= 1) acc += __shfl_xor_sync(0xffffffff, acc, off);
    if (lane == 0) out[(size_t)b * 1000 + c] = expf(ls[0]) * acc;
}

// =======================================================================
extern "C" void kernel_launch(void* const* d_in, const int* in_sizes, int n_in,
                              void* d_out, int out_size)
{
    const float* x   = (const float*)d_in[0];
    const float* txt = (const float*)d_in[1];
    const float* siw = (const float*)d_in[2];
    const float* sib = (const float*)d_in[3];
    const float* sow = (const float*)d_in[4];
    const float* sob = (const float*)d_in[5];
    const float* ciw = (const float*)d_in[6];
    const float* cib = (const float*)d_in[7];
    const float* cow = (const float*)d_in[8];
    const float* cob = (const float*)d_in[9];
    const float* ls  = (const float*)d_in[10];
    float* out = (float*)d_out;

    __half *p_aohi, *p_aolo, *p_sowhi, *p_sowlo, *p_xshi, *p_xslo;
    __half *p_W2hi, *p_W2lo, *p_qkh;
    float  *p_xs, *p_bqk;
    cudaGetSymbolAddress((void**)&p_aohi,  g_aohi);
    cudaGetSymbolAddress((void**)&p_aolo,  g_aolo);
    cudaGetSymbolAddress((void**)&p_sowhi, g_sowhi);
    cudaGetSymbolAddress((void**)&p_sowlo, g_sowlo);
    cudaGetSymbolAddress((void**)&p_xshi,  g_xshi);
    cudaGetSymbolAddress((void**)&p_xslo,  g_xslo);
    cudaGetSymbolAddress((void**)&p_W2hi,  g_W2hi);
    cudaGetSymbolAddress((void**)&p_W2lo,  g_W2lo);
    cudaGetSymbolAddress((void**)&p_qkh,   g_qkh);
    cudaGetSymbolAddress((void**)&p_xs,    g_xs);
    cudaGetSymbolAddress((void**)&p_bqk,   g_bqk);

    cudaFuncSetAttribute(self_attn_kernel, cudaFuncAttributeMaxDynamicSharedMemorySize, 74304);
    cudaFuncSetAttribute(attn_cls_s,       cudaFuncAttributeMaxDynamicSharedMemorySize, 82944);
    cudaFuncSetAttribute(rc_kernel,        cudaFuncAttributeMaxDynamicSharedMemorySize, 123392);

    // text -> fp16 (once)
    f2h_text<<<48000, 256>>>(txt);
    // conversions + cWqT + bqk + bov + g_part zero
    megaconv<<<2544, 256>>>(x, siw, sow, ciw, cow, cib, cob);
    // batched weight GEMMs
    hgemm3_w<<<416, 256>>>(sib);
    // self-attention
    self_attn_kernel<<<64, 128, 74304>>>();
    // xs = ao @ sow^T + sob
    hgemm3<<<dim3(8, 12), 256>>>(p_aohi, p_aolo, p_sowhi, p_sowlo, 1, sob, 1.f,
                                 p_xs, p_xshi, p_xslo, 512, 512);
    // qk = xs @ W2 + bqk
    hgemm3<<<dim3(8, 12), 256>>>(p_xshi, p_xslo, p_W2hi, p_W2lo, 0, p_bqk, 1.f,
                                 nullptr, p_qkh, nullptr, 512, 512);
    // S + softmax + layer-sum (2 CTAs/SM)
    attn_cls_s<<<1000, 256, 82944>>>();
    // rc = w @ text
    rc_kernel<<<1000, 256, 123392>>>();
    // projection + norms + logits
    txt_gemm_kernel<<<dim3(4, 500), 256>>>();
    make_h_kernel<<<64, 512>>>();
    logits_kernel<<<dim3(125, 64), 256>>>(ls, out);
}

// round 15
// speedup vs baseline: 1.6422x; 1.0250x over previous
#include <cuda_runtime.h>
#include <cuda_fp16.h>
#include <cstdint>
#include <mma.h>

using namespace nvcuda;

#define ATTN_SCALE 0.044194173824159216f  // 1/sqrt(512)
#define TH_LD 520
#define SS_LD 100
#define WLD   104

// ---------------- static device scratch ----------------
__device__ __align__(16) __half g_xhi  [768 * 512],   g_xlo  [768 * 512];
__device__ __align__(16) __half g_siwhi[1536 * 512],  g_siwlo[1536 * 512];
__device__ __align__(16) __half g_sowhi[512 * 512],   g_sowlo[512 * 512];
__device__ __align__(16) __half g_cWkhi[512 * 512],   g_cWklo[512 * 512];
__device__ __align__(16) __half g_cWvhi[512 * 512],   g_cWvlo[512 * 512];
__device__ __align__(16) __half g_cWqThi[512 * 512],  g_cWqTlo[512 * 512];
__device__ __align__(16) __half g_cowhi[512 * 512],   g_cowlo[512 * 512];
__device__ __align__(16) float  g_qkv  [768 * 1536];
__device__ __align__(16) __half g_aohi [768 * 512],   g_aolo [768 * 512];
__device__ __align__(16) float  g_xs   [768 * 512];
__device__ __align__(16) __half g_xshi [768 * 512],   g_xslo [768 * 512];
__device__ __align__(16) __half g_W2hi [512 * 512],   g_W2lo [512 * 512];
__device__ __align__(16) float  g_bqk  [512];
__device__ __align__(16) __half g_qkh  [768 * 512];
__device__ __align__(16) __half g_Wovh [512 * 512];
__device__ __align__(16) float  g_bov  [512];
__device__ __align__(16) __half g_texth[(size_t)1000 * 96 * 512];
__device__ __align__(16) __half g_w    [(size_t)1000 * 64 * 96];
__device__ __align__(16) __half g_rch  [(size_t)64 * 1000 * 512];
__device__ __align__(16) __half g_txth [(size_t)64 * 1000 * 512];
__device__ __align__(16) float  g_part [64 * 512];
__device__ __align__(16) float  g_h    [64 * 512];

// ---------------- helpers ----------------
__device__ __forceinline__ void cpasync16(uint32_t dst, const void* src) {
    asm volatile("cp.async.cg.shared.global [%0], [%1], 16;"
                 :: "r"(dst), "l"(__cvta_generic_to_global(src)));
}
__device__ __forceinline__ uint32_t smem_u32(const void* p) {
    uint32_t a;
    asm("{ .reg .u64 t; cvta.to.shared.u64 t, %1; cvt.u32.u64 %0, t; }" : "=r"(a) : "l"(p));
    return a;
}
#define CP_COMMIT() asm volatile("cp.async.commit_group;" ::: "memory")
#define CP_WAIT0()  asm volatile("cp.async.wait_group 0;" ::: "memory")

__device__ __forceinline__ void split_f(float x, __half& h, __half& l) {
    h = __float2half(x);
    l = __float2half(x - __half2float(h));
}

// =======================================================================
// MEGA conversion kernel (launch #1): text f2h + split-converts +
// transpose + bqk + bov + zero g_part. Block-range dispatch:
//   [0,48000)        : text fp32 -> fp16
//   [48000,50208)    : split converts + g_part zero
//   [50208,50464)    : cWq transpose-split
//   [50464,50480)    : bqk
//   [50480,50544)    : bov
// =======================================================================
__global__ void megaconv(const float* __restrict__ txt,
                         const float* __restrict__ x, const float* __restrict__ siw,
                         const float* __restrict__ sow, const float* __restrict__ ciw,
                         const float* __restrict__ cow, const float* __restrict__ cib,
                         const float* __restrict__ cob)
{
    __shared__ float sred[8][33];
    __shared__ float tt[32][33];
    const int blk = blockIdx.x, tid = threadIdx.x;

    if (blk < 48000) {
        size_t i = ((size_t)blk * 256 + tid) * 4;
        float4 v = *(const float4*)(txt + i);
        __half2* o = (__half2*)(g_texth + i);
        o[0] = __floats2half2_rn(v.x, v.y);
        o[1] = __floats2half2_rn(v.z, v.w);
    } else if (blk < 50208) {
        const size_t N1 = 98304, N2 = N1 + 196608, N3 = N2 + 65536, N4 = N3 + 65536,
                     N5 = N4 + 65536, N6 = N5 + 65536;
        size_t u = (size_t)(blk - 48000) * 256 + tid;
        if (u >= N6) { ((float4*)g_part)[u - N6] = make_float4(0.f, 0.f, 0.f, 0.f); return; }
        const float* src; __half* hi; __half* lo; size_t o;
        if (u < N1)      { src = x;                hi = g_xhi;   lo = g_xlo;   o = u; }
        else if (u < N2) { src = siw;              hi = g_siwhi; lo = g_siwlo; o = u - N1; }
        else if (u < N3) { src = sow;              hi = g_sowhi; lo = g_sowlo; o = u - N2; }
        else if (u < N4) { src = ciw + 512 * 512;  hi = g_cWkhi; lo = g_cWklo; o = u - N3; }
        else if (u < N5) { src = ciw + 1024 * 512; hi = g_cWvhi; lo = g_cWvlo; o = u - N4; }
        else             { src = cow;              hi = g_cowhi; lo = g_cowlo; o = u - N5; }
        float4 v = ((const float4*)src)[o];
        __half h0, l0, h1, l1, h2, l2, h3, l3;
        split_f(v.x, h0, l0); split_f(v.y, h1, l1);
        split_f(v.z, h2, l2); split_f(v.w, h3, l3);
        __half2* oh = (__half2*)(hi + o * 4);
        __half2* ol = (__half2*)(lo + o * 4);
        oh[0] = __halves2half2(h0, h1); oh[1] = __halves2half2(h2, h3);
        ol[0] = __halves2half2(l0, l1); ol[1] = __halves2half2(l2, l3);
    } else if (blk < 50464) {
        int b = blk - 50208;
        const int tx = tid & 31, ty = tid >> 5;
        const int bx = (b & 15) * 32, by = (b >> 4) * 32;
        #pragma unroll
        for (int j = 0; j < 4; j++)
            tt[ty + j * 8][tx] = ciw[(size_t)(by + ty + j * 8) * 512 + bx + tx];
        __syncthreads();
        #pragma unroll
        for (int j = 0; j < 4; j++) {
            float v = tt[tx][ty + j * 8];
            __half h, l; split_f(v, h, l);
            size_t o = (size_t)(bx + ty + j * 8) * 512 + by + tx;
            g_cWqThi[o] = h; g_cWqTlo[o] = l;
        }
    } else if (blk < 50480) {
        int b = blk - 50464;
        const int dd = tid & 31, eg = tid >> 5;
        const int d = b * 32 + dd;
        const float* cWk = ciw + 512 * 512;
        float s = 0.f;
        const int e0 = eg * 64;
        #pragma unroll 8
        for (int e = e0; e < e0 + 64; e++) s += cib[e] * cWk[(size_t)e * 512 + d];
        sred[eg][dd] = s;
        __syncthreads();
        if (eg == 0) {
            float t = 0.f;
            #pragma unroll
            for (int i = 0; i < 8; i++) t += sred[i][dd];
            g_bqk[d] = t * ATTN_SCALE;
        }
    } else {
        int b = blk - 50480;
        int warp = tid >> 5, lane = tid & 31;
        int i = b * 8 + warp;
        const float* cbv = cib + 1024;
        float s = 0.f;
        for (int e = lane; e < 512; e += 32) s += cow[i * 512 + e] * cbv[e];
        #pragma unroll
        for (int o = 16; o > 0; o >>= 1) s += __shfl_xor_sync(0xffffffff, s, o);
        if (lane == 0) g_bov[i] = s + cob[i];
    }
}

// =======================================================================
// Split-fp16 GEMM body
// =======================================================================
__device__ __forceinline__ void hg3_body(
    __half* Ash, __half* Asl, __half* Bsh, __half* Bsl, float* Cs,
    const __half* __restrict__ Ahi, const __half* __restrict__ Alo,
    const __half* __restrict__ Bhi, const __half* __restrict__ Blo, int bt,
    const float* __restrict__ bias, float scale,
    float* __restrict__ Cf, __half* __restrict__ Chi, __half* __restrict__ Clo,
    int N, int K, int m0, int n0)
{
    const int tid = threadIdx.x, warp = tid >> 5;
    const int wr = warp >> 1, wc = warp & 1;

    wmma::fragment<wmma::accumulator, 16, 16, 16, float> acc[2];
    wmma::fill_fragment(acc[0], 0.f);
    wmma::fill_fragment(acc[1], 0.f);

    uint4 rah[2], ral[2], rbh[2], rbl[2];
    #pragma unroll
    for (int i = 0; i < 2; i++) {
        int f = tid + i * 256, r = f >> 3, v = f & 7;
        rah[i] = ((const uint4*)(Ahi + (size_t)(m0 + r) * K))[v];
        ral[i] = ((const uint4*)(Alo + (size_t)(m0 + r) * K))[v];
        if (bt) {
            rbh[i] = ((const uint4*)(Bhi + (size_t)(n0 + r) * K))[v];
            rbl[i] = ((const uint4*)(Blo + (size_t)(n0 + r) * K))[v];
        } else {
            rbh[i] = ((const uint4*)(Bhi + (size_t)r * N + n0))[v];
            rbl[i] = ((const uint4*)(Blo + (size_t)r * N + n0))[v];
        }
    }
    const int nk = K >> 6;
    for (int kc = 0; kc < nk; kc++) {
        #pragma unroll
        for (int i = 0; i < 2; i++) {
            int f = tid + i * 256, r = f >> 3, v = f & 7;
            *((uint4*)(Ash + r * 72) + v) = rah[i];
            *((uint4*)(Asl + r * 72) + v) = ral[i];
            *((uint4*)(Bsh + r * 72) + v) = rbh[i];
            *((uint4*)(Bsl + r * 72) + v) = rbl[i];
        }
        __syncthreads();
        if (kc + 1 < nk) {
            int kk = (kc + 1) << 6;
            #pragma unroll
            for (int i = 0; i < 2; i++) {
                int f = tid + i * 256, r = f >> 3, v = f & 7;
                rah[i] = ((const uint4*)(Ahi + (size_t)(m0 + r) * K + kk))[v];
                ral[i] = ((const uint4*)(Alo + (size_t)(m0 + r) * K + kk))[v];
                if (bt) {
                    rbh[i] = ((const uint4*)(Bhi + (size_t)(n0 + r) * K + kk))[v];
                    rbl[i] = ((const uint4*)(Blo + (size_t)(n0 + r) * K + kk))[v];
                } else {
                    rbh[i] = ((const uint4*)(Bhi + (size_t)(kk + r) * N + n0))[v];
                    rbl[i] = ((const uint4*)(Blo + (size_t)(kk + r) * N + n0))[v];
                }
            }
        }
        #pragma unroll
        for (int ks = 0; ks < 4; ks++) {
            wmma::fragment<wmma::matrix_a, 16, 16, 16, __half, wmma::row_major> afh, afl;
            wmma::load_matrix_sync(afh, Ash + (wr * 16) * 72 + ks * 16, 72);
            wmma::load_matrix_sync(afl, Asl + (wr * 16) * 72 + ks * 16, 72);
            #pragma unroll
            for (int j = 0; j < 2; j++) {
                if (bt) {
                    wmma::fragment<wmma::matrix_b, 16, 16, 16, __half, wmma::col_major> bfh, bfl;
                    wmma::load_matrix_sync(bfh, Bsh + ((wc * 2 + j) * 16) * 72 + ks * 16, 72);
                    wmma::load_matrix_sync(bfl, Bsl + ((wc * 2 + j) * 16) * 72 + ks * 16, 72);
                    wmma::mma_sync(acc[j], afh, bfh, acc[j]);
                    wmma::mma_sync(acc[j], afh, bfl, acc[j]);
                    wmma::mma_sync(acc[j], afl, bfh, acc[j]);
                } else {
                    wmma::fragment<wmma::matrix_b, 16, 16, 16, __half, wmma::row_major> bfh, bfl;
                    wmma::load_matrix_sync(bfh, Bsh + (ks * 16) * 72 + (wc * 2 + j) * 16, 72);
                    wmma::load_matrix_sync(bfl, Bsl + (ks * 16) * 72 + (wc * 2 + j) * 16, 72);
                    wmma::mma_sync(acc[j], afh, bfh, acc[j]);
                    wmma::mma_sync(acc[j], afh, bfl, acc[j]);
                    wmma::mma_sync(acc[j], afl, bfh, acc[j]);
                }
            }
        }
        __syncthreads();
    }
    wmma::store_matrix_sync(Cs + (wr * 16) * 68 + wc * 32,      acc[0], 68, wmma::mem_row_major);
    wmma::store_matrix_sync(Cs + (wr * 16) * 68 + wc * 32 + 16, acc[1], 68, wmma::mem_row_major);
    __syncthreads();
    for (int i = tid; i < 4096; i += 256) {
        int r = i >> 6, n = i & 63;
        float v = Cs[r * 68 + n] * scale + (bias ? bias[n0 + n] : 0.f);
        size_t m = m0 + r;
        if (Cf)  Cf[m * N + n0 + n] = v;
        if (Chi) {
            __half h = __float2half(v);
            Chi[m * N + n0 + n] = h;
            if (Clo) Clo[m * N + n0 + n] = __float2half(v - __half2float(h));
        }
    }
}

__global__ void hgemm3(const __half* Ahi, const __half* Alo,
                       const __half* Bhi, const __half* Blo, int bt,
                       const float* bias, float scale,
                       float* Cf, __half* Chi, __half* Clo, int N, int K)
{
    __shared__ __half Ash[64 * 72], Asl[64 * 72], Bsh[64 * 72], Bsl[64 * 72];
    __shared__ float  Cs[64 * 68];
    hg3_body(Ash, Asl, Bsh, Bsl, Cs, Ahi, Alo, Bhi, Blo, bt, bias, scale,
             Cf, Chi, Clo, N, K, blockIdx.y * 64, blockIdx.x * 64);
}

__global__ void hgemm3_w(const float* __restrict__ sib)
{
    __shared__ __half Ash[64 * 72], Asl[64 * 72], Bsh[64 * 72], Bsl[64 * 72];
    __shared__ float  Cs[64 * 68];
    int id = blockIdx.x;
    if (id < 288) {
        hg3_body(Ash, Asl, Bsh, Bsl, Cs, g_xhi, g_xlo, g_siwhi, g_siwlo, 1, sib, 1.f,
                 g_qkv, nullptr, nullptr, 1536, 512, (id / 24) * 64, (id % 24) * 64);
    } else if (id < 352) {
        id -= 288;
        hg3_body(Ash, Asl, Bsh, Bsl, Cs, g_cWqThi, g_cWqTlo, g_cWkhi, g_cWklo, 0, nullptr,
                 ATTN_SCALE, nullptr, g_W2hi, g_W2lo, 512, 512, (id / 8) * 64, (id % 8) * 64);
    } else {
        id -= 352;
        hg3_body(Ash, Asl, Bsh, Bsl, Cs, g_cowhi, g_cowlo, g_cWvhi, g_cWvlo, 0, nullptr,
                 1.f, nullptr, g_Wovh, nullptr, 512, 512, (id / 8) * 64, (id % 8) * 64);
    }
}

// =======================================================================
// self-attention: 256 threads, warp-per-dot-product S.
// =======================================================================
__global__ void self_attn_kernel()
{
    extern __shared__ float sh[];
    float* q = sh;
    float* k = q + 12 * 512;
    float* v = k + 12 * 512;
    float* S = v + 12 * 512;
    const int b = blockIdx.x, tid = threadIdx.x;
    const int warp = tid >> 5, lane = tid & 31;

    for (int i = tid; i < 12 * 512; i += 256) {
        int l = i >> 9, d = i & 511;
        const float* row = g_qkv + (size_t)(l * 64 + b) * 1536;
        q[i] = row[d]; k[i] = row[512 + d]; v[i] = row[1024 + d];
    }
    __syncthreads();
    // S: 144 dots, warp-parallel (18 per warp), shfl reduce
    for (int i = warp; i < 144; i += 8) {
        int l = i / 12, m = i - l * 12;
        const float* qp = q + l * 512;
        const float* kp = k + m * 512;
        float s = 0.f;
        #pragma unroll 4
        for (int e = lane; e < 512; e += 32) s += qp[e] * kp[e];
        #pragma unroll
        for (int o = 16; o > 0; o >>= 1) s += __shfl_xor_sync(0xffffffff, s, o);
        if (lane == 0) S[i] = s * ATTN_SCALE;
    }
    __syncthreads();
    if (tid < 12) {
        float mx = -1e30f;
        for (int m = 0; m < 12; m++) mx = fmaxf(mx, S[tid * 12 + m]);
        float e[12], sum = 0.f;
        for (int m = 0; m < 12; m++) { e[m] = expf(S[tid * 12 + m] - mx); sum += e[m]; }
        float inv = 1.f / sum;
        for (int m = 0; m < 12; m++) S[tid * 12 + m] = e[m] * inv;
    }
    __syncthreads();
    for (int i = tid; i < 12 * 512; i += 256) {
        int l = i >> 9, d = i & 511;
        float o = 0.f;
        #pragma unroll
        for (int m = 0; m < 12; m++) o += S[l * 12 + m] * v[m * 512 + d];
        __half h, lo; split_f(o, h, lo);
        size_t idx = (size_t)(b * 12 + l) * 512 + d;
        g_aohi[idx] = h; g_aolo[idx] = lo;
    }
}

// =======================================================================
// S-kernel: stream q AND text k-chunks, 2 CTAs/SM (R13, best measured).
// =======================================================================
#define SAQ 0
#define STH 55296

__global__ void __launch_bounds__(256, 2) attn_cls_s()
{
    extern __shared__ char smc[];
    const uint32_t sb = smem_u32(smc);
    float* Ss = (float*)smc;
    const int tid  = threadIdx.x;
    const int warp = tid >> 5;
    const int c    = blockIdx.x;
    const int wr = warp >> 1, wc = warp & 1;
    const __half* tbase = g_texth + (size_t)c * 96 * 512;

    for (int mch = 0; mch < 4; mch++) {
        const __half* qbase = g_qkh + (size_t)(mch * 192) * 512;

        #pragma unroll
        for (int i = 0; i < 6; i++) {
            int f = tid + i * 256, r = f >> 3, v = f & 7;
            cpasync16(sb + SAQ + r * 144 + v * 16, qbase + (size_t)r * 512 + v * 8);
        }
        #pragma unroll
        for (int i = 0; i < 3; i++) {
            int f = tid + i * 256, r = f >> 3, v = f & 7;
            cpasync16(sb + STH + r * 144 + v * 16, tbase + (size_t)r * 512 + v * 8);
        }
        CP_COMMIT();

        wmma::fragment<wmma::accumulator, 16, 16, 16, float> acc[3][3];
        #pragma unroll
        for (int i = 0; i < 3; i++)
            #pragma unroll
            for (int j = 0; j < 3; j++) wmma::fill_fragment(acc[i][j], 0.f);

        for (int kc = 0; kc < 8; kc++) {
            CP_WAIT0();
            __syncthreads();
            if (kc < 7) {
                int nb = (kc + 1) & 1;
                int kk = (kc + 1) * 64;
                #pragma unroll
                for (int i = 0; i < 6; i++) {
                    int f = tid + i * 256, r = f >> 3, v = f & 7;
                    cpasync16(sb + SAQ + nb * 27648 + r * 144 + v * 16,
                              qbase + (size_t)r * 512 + kk + v * 8);
                }
                #pragma unroll
                for (int i = 0; i < 3; i++) {
                    int f = tid + i * 256, r = f >> 3, v = f & 7;
                    cpasync16(sb + STH + nb * 13824 + r * 144 + v * 16,
                              tbase + (size_t)r * 512 + kk + v * 8);
                }
                CP_COMMIT();
            }
            const __half* aq = (const __half*)(smc + SAQ + (kc & 1) * 27648);
            const __half* th = (const __half*)(smc + STH + (kc & 1) * 13824);
            #pragma unroll
            for (int ks = 0; ks < 4; ks++) {
                wmma::fragment<wmma::matrix_a, 16, 16, 16, __half, wmma::row_major> af[3];
                #pragma unroll
                for (int i = 0; i < 3; i++)
                    wmma::load_matrix_sync(af[i], aq + ((wr * 3 + i) * 16) * 72 + ks * 16, 72);
                #pragma unroll
                for (int j = 0; j < 3; j++) {
                    wmma::fragment<wmma::matrix_b, 16, 16, 16, __half, wmma::col_major> bf;
                    wmma::load_matrix_sync(bf, th + ((wc * 3 + j) * 16) * 72 + ks * 16, 72);
                    #pragma unroll
                    for (int i = 0; i < 3; i++) wmma::mma_sync(acc[i][j], af[i], bf, acc[i][j]);
                }
            }
        }
        __syncthreads();
        #pragma unroll
        for (int i = 0; i < 3; i++)
            #pragma unroll
            for (int j = 0; j < 3; j++)
                wmma::store_matrix_sync(Ss + ((wr * 3 + i) * 16) * SS_LD + (wc * 3 + j) * 16,
                                        acc[i][j], SS_LD, wmma::mem_row_major);
        __syncthreads();

        if (tid < 128) {
            int bl = tid >> 3, t = tid & 7;
            float wacc[12];
            #pragma unroll
            for (int m = 0; m < 12; m++) wacc[m] = 0.f;
            for (int l = 0; l < 12; l++) {
                int base = (bl * 12 + l) * SS_LD + t;
                float vals[12], mx = -1e30f;
                #pragma unroll
                for (int m = 0; m < 12; m++) { vals[m] = Ss[base + m * 8]; mx = fmaxf(mx, vals[m]); }
                float sum = 0.f;
                #pragma unroll
                for (int m = 0; m < 12; m++) { vals[m] = __expf(vals[m] - mx); sum += vals[m]; }
                float inv = 1.f / sum;
                #pragma unroll
                for (int m = 0; m < 12; m++) wacc[m] += vals[m] * inv;
            }
            __half* wrow = g_w + ((size_t)c * 64 + mch * 16 + bl) * 96;
            #pragma unroll
            for (int m = 0; m < 12; m++)
                wrow[m * 8 + t] = __float2half(wacc[m] * (1.f / 96.f));
        }
        __syncthreads();
    }
}

// =======================================================================
// rc = w @ text per class. grid 1000, 256 thr. dyn smem 123392.
// =======================================================================
__global__ void rc_kernel()
{
    extern __shared__ char sm[];
    __half* th = (__half*)sm;
    __half* ws = (__half*)(sm + 99840);
    float*  stg = (float*)(sm + 99840 + 13312);
    const int tid = threadIdx.x, warp = tid >> 5, lane = tid & 31;
    const int c = blockIdx.x;

    const __half* tsrc = g_texth + (size_t)c * 96 * 512;
    for (int i = tid; i < 96 * 64; i += 256) {
        int p = i >> 6, v = i & 63;
        *((uint4*)(th + p * TH_LD) + v) = ((const uint4*)(tsrc + (size_t)p * 512))[v];
    }
    for (int i = tid; i < 768; i += 256) {
        int r = i / 12, v = i - r * 12;
        *((uint4*)(ws + r * WLD) + v) = ((const uint4*)(g_w + ((size_t)c * 64 + r) * 96))[v];
    }
    __syncthreads();

    const int n0w = warp * 64;
    wmma::fragment<wmma::accumulator, 16, 16, 16, float> acc[4][4];
    #pragma unroll
    for (int i = 0; i < 4; i++)
        #pragma unroll
        for (int j = 0; j < 4; j++) wmma::fill_fragment(acc[i][j], 0.f);
    #pragma unroll
    for (int kt = 0; kt < 6; kt++) {
        wmma::fragment<wmma::matrix_a, 16, 16, 16, __half, wmma::row_major> af[4];
        #pragma unroll
        for (int i = 0; i < 4; i++)
            wmma::load_matrix_sync(af[i], ws + (i * 16) * WLD + kt * 16, WLD);
        #pragma unroll
        for (int j = 0; j < 4; j++) {
            wmma::fragment<wmma::matrix_b, 16, 16, 16, __half, wmma::row_major> bf;
            wmma::load_matrix_sync(bf, th + (kt * 16) * TH_LD + n0w + j * 16, TH_LD);
            #pragma unroll
            for (int i = 0; i < 4; i++) wmma::mma_sync(acc[i][j], af[i], bf, acc[i][j]);
        }
    }
    float* mystg = stg + warp * 320;
    #pragma unroll
    for (int i = 0; i < 4; i++)
        #pragma unroll
        for (int j = 0; j < 4; j++) {
            wmma::store_matrix_sync(mystg, acc[i][j], 20, wmma::mem_row_major);
            __syncwarp();
            #pragma unroll
            for (int e = 0; e < 8; e++) {
                int f = lane + e * 32, r = f >> 4, cc = f & 15;
                g_rch[((size_t)(i * 16 + r) * 1000 + c) * 512 + n0w + j * 16 + cc] =
                    __float2half(mystg[r * 20 + cc]);
            }
            __syncwarp();
        }
}

// =======================================================================
// txt = rc @ Wov^T + bov -> fp16, fused column-sq-sums. grid (4,500).
// =======================================================================
__global__ void txt_gemm_kernel()
{
    __shared__ __half As[128 * 72];
    __shared__ __half Bs[128 * 72];
    __shared__ float  stg[8][16 * 20];
    __shared__ float  sq[2][128];
    const int tid = threadIdx.x, warp = tid >> 5, lane = tid & 31;
    const size_t m0 = (size_t)blockIdx.y * 128;
    const int n0 = blockIdx.x * 128;
    const int wr = warp >> 1, wc = warp & 1;
    const int b0f = (int)(m0 / 1000);
    uint4 ra[4], rb[4];
    wmma::fragment<wmma::accumulator, 16, 16, 16, float> acc[2][4];
    #pragma unroll
    for (int i = 0; i < 2; i++)
        #pragma unroll
        for (int j = 0; j < 4; j++) wmma::fill_fragment(acc[i][j], 0.f);

    #pragma unroll
    for (int i = 0; i < 4; i++) {
        int f = tid + i * 256, r = f >> 3, v = f & 7;
        ra[i] = ((const uint4*)(g_rch + (m0 + r) * 512))[v];
        rb[i] = ((const uint4*)(g_Wovh + (size_t)(n0 + r) * 512))[v];
    }
    for (int kc = 0; kc < 8; kc++) {
        #pragma unroll
        for (int i = 0; i < 4; i++) {
            int f = tid + i * 256, r = f >> 3, v = f & 7;
            *((uint4*)(As + r * 72) + v) = ra[i];
            *((uint4*)(Bs + r * 72) + v) = rb[i];
        }
        __syncthreads();
        if (kc < 7) {
            int kk = (kc + 1) * 64;
            #pragma unroll
            for (int i = 0; i < 4; i++) {
                int f = tid + i * 256, r = f >> 3, v = f & 7;
                ra[i] = ((const uint4*)(g_rch + (m0 + r) * 512 + kk))[v];
                rb[i] = ((const uint4*)(g_Wovh + (size_t)(n0 + r) * 512 + kk))[v];
            }
        }
        #pragma unroll
        for (int ks = 0; ks < 4; ks++) {
            wmma::fragment<wmma::matrix_a, 16, 16, 16, __half, wmma::row_major> af[2];
            #pragma unroll
            for (int i = 0; i < 2; i++)
                wmma::load_matrix_sync(af[i], As + ((wr * 2 + i) * 16) * 72 + ks * 16, 72);
            #pragma unroll
            for (int j = 0; j < 4; j++) {
                wmma::fragment<wmma::matrix_b, 16, 16, 16, __half, wmma::col_major> bf;
                wmma::load_matrix_sync(bf, Bs + ((wc * 4 + j) * 16) * 72 + ks * 16, 72);
                #pragma unroll
                for (int i = 0; i < 2; i++) wmma::mma_sync(acc[i][j], af[i], bf, acc[i][j]);
            }
        }
        __syncthreads();
    }
    ((float*)sq)[tid] = 0.f;
    __syncthreads();
    float sq0[4] = {0.f, 0.f, 0.f, 0.f};
    float sq1[4] = {0.f, 0.f, 0.f, 0.f};
    #pragma unroll
    for (int i = 0; i < 2; i++)
        #pragma unroll
        for (int j = 0; j < 4; j++) {
            wmma::store_matrix_sync(stg[warp], acc[i][j], 20, wmma::mem_row_major);
            __syncwarp();
            #pragma unroll
            for (int e = 0; e < 8; e++) {
                int f = lane + e * 32, r = f >> 4, cc = f & 15;
                int n = n0 + (wc * 4 + j) * 16 + cc;
                size_t m = m0 + (wr * 2 + i) * 16 + r;
                float v = stg[warp][r * 20 + cc] + g_bov[n];
                g_txth[m * 512 + n] = __float2half(v);
                int bb = (int)(m / 1000) - b0f;
                if (bb == 0) sq0[j] += v * v; else sq1[j] += v * v;
            }
            __syncwarp();
        }
    #pragma unroll
    for (int j = 0; j < 4; j++) {
        int nl = (wc * 4 + j) * 16 + (lane & 15);
        atomicAdd(&sq[0][nl], sq0[j]);
        atomicAdd(&sq[1][nl], sq1[j]);
    }
    __syncthreads();
    if (tid < 128) {
        #pragma unroll
        for (int s = 0; s < 2; s++) {
            int b = b0f + s;
            if (b < 64) atomicAdd(&g_part[b * 512 + n0 + tid], sq[s][tid]);
        }
    }
}

__global__ void make_h_kernel()
{
    __shared__ float red[512];
    const int b = blockIdx.x, d = threadIdx.x;
    float nrm2 = g_part[b * 512 + d];
    float iv = g_xs[(size_t)(b * 12 + 11) * 512 + d];
    red[d] = iv * iv;
    __syncthreads();
    for (int s = 256; s > 0; s >>= 1) {
        if (d < s) red[d] += red[d + s];
        __syncthreads();
    }
    g_h[b * 512 + d] = iv * rsqrtf(red[0]) * rsqrtf(nrm2);
}

__global__ void logits_kernel(const float* __restrict__ ls, float* __restrict__ out)
{
    __shared__ float hs[512];
    const int b = blockIdx.y;
    const int tid = threadIdx.x, warp = tid >> 5, lane = tid & 31;
    const int c = blockIdx.x * 8 + warp;
    for (int i = tid; i < 512; i += 256) hs[i] = g_h[b * 512 + i];
    __syncthreads();
    const __half2* row = (const __half2*)g_txth + ((size_t)b * 1000 + c) * 256;
    float acc = 0.f;
    for (int kk = lane; kk < 256; kk += 32) {
        float2 f = __half22float2(row[kk]);
        acc += hs[kk * 2] * f.x + hs[kk * 2 + 1] * f.y;
    }
    #pragma unroll
    for (int off = 16; off > 0; off >>= 1) acc += __shfl_xor_sync(0xffffffff, acc, off);
    if (lane == 0) out[(size_t)b * 1000 + c] = expf(ls[0]) * acc;
}

// =======================================================================
extern "C" void kernel_launch(void* const* d_in, const int* in_sizes, int n_in,
                              void* d_out, int out_size)
{
    const float* x   = (const float*)d_in[0];
    const float* txt = (const float*)d_in[1];
    const float* siw = (const float*)d_in[2];
    const float* sib = (const float*)d_in[3];
    const float* sow = (const float*)d_in[4];
    const float* sob = (const float*)d_in[5];
    const float* ciw = (const float*)d_in[6];
    const float* cib = (const float*)d_in[7];
    const float* cow = (const float*)d_in[8];
    const float* cob = (const float*)d_in[9];
    const float* ls  = (const float*)d_in[10];
    float* out = (float*)d_out;

    __half *p_aohi, *p_aolo, *p_sowhi, *p_sowlo, *p_xshi, *p_xslo;
    __half *p_W2hi, *p_W2lo, *p_qkh;
    float  *p_xs, *p_bqk;
    cudaGetSymbolAddress((void**)&p_aohi,  g_aohi);
    cudaGetSymbolAddress((void**)&p_aolo,  g_aolo);
    cudaGetSymbolAddress((void**)&p_sowhi, g_sowhi);
    cudaGetSymbolAddress((void**)&p_sowlo, g_sowlo);
    cudaGetSymbolAddress((void**)&p_xshi,  g_xshi);
    cudaGetSymbolAddress((void**)&p_xslo,  g_xslo);
    cudaGetSymbolAddress((void**)&p_W2hi,  g_W2hi);
    cudaGetSymbolAddress((void**)&p_W2lo,  g_W2lo);
    cudaGetSymbolAddress((void**)&p_qkh,   g_qkh);
    cudaGetSymbolAddress((void**)&p_xs,    g_xs);
    cudaGetSymbolAddress((void**)&p_bqk,   g_bqk);

    cudaFuncSetAttribute(self_attn_kernel, cudaFuncAttributeMaxDynamicSharedMemorySize, 74304);
    cudaFuncSetAttribute(attn_cls_s,       cudaFuncAttributeMaxDynamicSharedMemorySize, 82944);
    cudaFuncSetAttribute(rc_kernel,        cudaFuncAttributeMaxDynamicSharedMemorySize, 123392);

    // #1: text f2h + conversions + cWqT + bqk + bov + g_part zero
    megaconv<<<50544, 256>>>(txt, x, siw, sow, ciw, cow, cib, cob);
    // #2: batched weight GEMMs
    hgemm3_w<<<416, 256>>>(sib);
    // #3: self-attention (warp-parallel)
    self_attn_kernel<<<64, 256, 74304>>>();
    // #4: xs = ao @ sow^T + sob
    hgemm3<<<dim3(8, 12), 256>>>(p_aohi, p_aolo, p_sowhi, p_sowlo, 1, sob, 1.f,
                                 p_xs, p_xshi, p_xslo, 512, 512);
    // #5: qk = xs @ W2 + bqk
    hgemm3<<<dim3(8, 12), 256>>>(p_xshi, p_xslo, p_W2hi, p_W2lo, 0, p_bqk, 1.f,
                                 nullptr, p_qkh, nullptr, 512, 512);
    // #6: S + softmax + layer-sum (2 CTAs/SM)
    attn_cls_s<<<1000, 256, 82944>>>();
    // #7: rc = w @ text
    rc_kernel<<<1000, 256, 123392>>>();
    // #8-#10
    txt_gemm_kernel<<<dim3(4, 500), 256>>>();
    make_h_kernel<<<64, 512>>>();
    logits_kernel<<<dim3(125, 64), 256>>>(ls, out);
}